// round 9
// baseline (speedup 1.0000x reference)
#include <cuda_runtime.h>
#include <cuda_bf16.h>
#include <cuda_fp16.h>
#include <cstdint>

#define MAXN 100000
#define MAXE 1600000

// ---------------- scratch (device globals; no allocation allowed) ----------
// B packed: [half(2)][split(2)][kchunk(8)][n(128)][16 bf16] = 131072 bytes
__device__ __align__(16) uint8_t g_Bpk[131072];
__device__ __align__(16) float  g_self[MAXN * 128];
__device__ __align__(16) __half g_vwh[MAXN * 128];     // fp16 vw for edge gather
__device__ __align__(16) float  g_a0[MAXN * 4];
__device__ __align__(16) float  g_a1[MAXN * 4];
__device__ int   g_cnt[MAXN];                          // FULL degree per dest row
__device__ int   g_start[MAXN];
__device__ int   g_cursor[MAXN];
__device__ int   g_ticket;                             // scan tile ticket
__device__ volatile unsigned int g_state[512];         // (status<<30)|sum
__device__ unsigned int g_ecol[MAXE];
__device__ __align__(8) __half g_ewh[MAXE * 4];        // compacted per-record fp16 weights

// ---------------- helpers ---------------------------------------------------
__device__ __forceinline__ uint32_t smem_u32(const void* p) {
    uint32_t a;
    asm("{ .reg .u64 t; cvta.to.shared.u64 t, %1; cvt.u32.u64 %0, t; }" : "=r"(a) : "l"(p));
    return a;
}
__device__ __forceinline__ void ldsm4(uint32_t addr, uint32_t& r0, uint32_t& r1,
                                      uint32_t& r2, uint32_t& r3) {
    asm volatile("ldmatrix.sync.aligned.m8n8.x4.shared.b16 {%0,%1,%2,%3}, [%4];"
                 : "=r"(r0), "=r"(r1), "=r"(r2), "=r"(r3) : "r"(addr));
}
__device__ __forceinline__ void mma16816(float* c, uint32_t a0, uint32_t a1, uint32_t a2,
                                         uint32_t a3, uint32_t b0, uint32_t b1) {
    asm volatile(
        "mma.sync.aligned.m16n8k16.row.col.f32.bf16.bf16.f32 "
        "{%0,%1,%2,%3},{%4,%5,%6,%7},{%8,%9},{%0,%1,%2,%3};"
        : "+f"(c[0]), "+f"(c[1]), "+f"(c[2]), "+f"(c[3])
        : "r"(a0), "r"(a1), "r"(a2), "r"(a3), "r"(b0), "r"(b1));
}

// SMEM: B resident [hf(2)][sp(2)][kc(8)][128][32B] = 131072
//       A [sp(2)][kc(8)][row(128)][32B]            = 65536
//       ex: 128 rows x 4 colgroups x float2        = 4096
#define SMEM_B 0
#define SMEM_A 131072
#define SMEM_EX (131072 + 65536)
#define SMEM_TOTAL (131072 + 65536 + 4096)

// ---------------- kernel 0: pack B (bf16 hi/lo) + zero cnt/scan state ------
__global__ __launch_bounds__(256) void pack_kernel(const float* __restrict__ W0,
                                                   const float* __restrict__ W1, int n) {
    int idx = blockIdx.x * 256 + threadIdx.x;
    if (idx < 32768) {
        int k = idx >> 8;          // 0..127
        int c = idx & 255;         // 0..255 global output col
        float v;
        if (c < 128) {
            v = W0[k * 128 + c];
        } else {
            int j = c - 128;
            int h = j >> 5;
            int k2 = j & 31;
            v = W1[(h * 128 + k) * 32 + k2];
        }
        __nv_bfloat16 hi = __float2bfloat16_rn(v);
        __nv_bfloat16 lo = __float2bfloat16_rn(v - __bfloat162float(hi));
        int hf = c >> 7;
        int nn = c & 127;
        int kc = k >> 4;
        int kk = k & 15;
        int base = ((hf * 2 + 0) * 8 + kc) * 4096 + nn * 32 + kk * 2;
        *reinterpret_cast<__nv_bfloat16*>(g_Bpk + base) = hi;
        *reinterpret_cast<__nv_bfloat16*>(g_Bpk + base + 32768) = lo;   // sp stride = 8*4096
    }
    if (idx < n) g_cnt[idx] = 0;
    if (idx < 512) g_state[idx] = 0;
    if (idx == 0) g_ticket = 0;
}

// ---------------- kernel 1: persistent fused-pass GEMM, 16 warps ------------
__global__ __launch_bounds__(512, 1) void gemm_tc_kernel(
    const float* __restrict__ vecs, const float* __restrict__ b0,
    const float* __restrict__ att0, const float* __restrict__ att1,
    const float* __restrict__ attb0, const float* __restrict__ attb1,
    const float* __restrict__ off0, const float* __restrict__ sc0, int n, int ntiles) {
    extern __shared__ __align__(1024) char smem[];
    uint32_t sb = smem_u32(smem);
    float2* ex = reinterpret_cast<float2*>(smem + SMEM_EX);
    int tid = threadIdx.x;
    int wid = tid >> 5;
    int lane = tid & 31;

    int mg = wid & 3;            // row group: 32 rows
    int cg = wid >> 2;           // col group: 32 cols (== head index in vw half)
    int mrow0 = mg * 32;
    int ncol0 = cg * 32;
    int rq = lane >> 2;          // row-in-8
    int cq = 2 * (lane & 3);     // col pair

    int lt = lane >> 3;
    int l7 = lane & 7;
    int alane = ((lt & 1) * 8 + l7) * 32 + (lt >> 1) * 16;
    int blane = ((lt >> 1) * 8 + l7) * 32 + (lt & 1) * 16;

    // ---- load full B (131072 B) once, resident for kernel lifetime ----
    {
        const uint4* src = reinterpret_cast<const uint4*>(g_Bpk);
        uint4* dst = reinterpret_cast<uint4*>(smem + SMEM_B);
#pragma unroll
        for (int i = 0; i < 16; i++) dst[tid + i * 512] = __ldg(&src[tid + i * 512]);
    }
    __syncthreads();

    for (int tile = blockIdx.x; tile < ntiles; tile += gridDim.x) {
        int row0 = tile * 128;

        // ---- load A tile: fp32 -> bf16 hi/lo, [sp][kc][row][32B] ----
#pragma unroll
        for (int it = 0; it < 8; it++) {
            int t = it * 512 + tid;
            int r = t >> 5;
            int q = t & 31;
            float4 v = make_float4(0.f, 0.f, 0.f, 0.f);
            int gr = row0 + r;
            if (gr < n) v = __ldg(reinterpret_cast<const float4*>(vecs + (size_t)gr * 128 + q * 4));
            __nv_bfloat16 h0 = __float2bfloat16_rn(v.x), h1 = __float2bfloat16_rn(v.y);
            __nv_bfloat16 h2 = __float2bfloat16_rn(v.z), h3 = __float2bfloat16_rn(v.w);
            __nv_bfloat16 l0 = __float2bfloat16_rn(v.x - __bfloat162float(h0));
            __nv_bfloat16 l1 = __float2bfloat16_rn(v.y - __bfloat162float(h1));
            __nv_bfloat16 l2 = __float2bfloat16_rn(v.z - __bfloat162float(h2));
            __nv_bfloat16 l3 = __float2bfloat16_rn(v.w - __bfloat162float(h3));
            uint2 hv, lv;
            hv.x = ((uint32_t)__bfloat16_as_ushort(h1) << 16) | __bfloat16_as_ushort(h0);
            hv.y = ((uint32_t)__bfloat16_as_ushort(h3) << 16) | __bfloat16_as_ushort(h2);
            lv.x = ((uint32_t)__bfloat16_as_ushort(l1) << 16) | __bfloat16_as_ushort(l0);
            lv.y = ((uint32_t)__bfloat16_as_ushort(l3) << 16) | __bfloat16_as_ushort(l2);
            int kc = q >> 2;
            int kq = q & 3;
            int off = kc * 4096 + r * 32 + kq * 8;
            *reinterpret_cast<uint2*>(smem + SMEM_A + off) = hv;
            *reinterpret_cast<uint2*>(smem + SMEM_A + 32768 + off) = lv;
        }
        __syncthreads();

        // ---- fused compute: both col-halves in one k loop ----
        float acc[2][2][4][4];   // [hf][mt][nf][q]
#pragma unroll
        for (int hf = 0; hf < 2; hf++)
#pragma unroll
            for (int mt = 0; mt < 2; mt++)
#pragma unroll
                for (int nf = 0; nf < 4; nf++)
#pragma unroll
                    for (int q = 0; q < 4; q++) acc[hf][mt][nf][q] = 0.f;

#pragma unroll
        for (int kc = 0; kc < 8; kc++) {
            uint32_t ah[2][4], al[2][4];
#pragma unroll
            for (int mt = 0; mt < 2; mt++) {
                uint32_t aaddr = sb + SMEM_A + kc * 4096 + (mrow0 + mt * 16) * 32 + alane;
                ldsm4(aaddr, ah[mt][0], ah[mt][1], ah[mt][2], ah[mt][3]);
                ldsm4(aaddr + 32768, al[mt][0], al[mt][1], al[mt][2], al[mt][3]);
            }
#pragma unroll
            for (int hf = 0; hf < 2; hf++)
#pragma unroll
                for (int np = 0; np < 2; np++) {
                    uint32_t bh[4], bl[4];
                    uint32_t baddr = sb + SMEM_B + hf * 65536 + kc * 4096 +
                                     (ncol0 + np * 16) * 32 + blane;
                    ldsm4(baddr, bh[0], bh[1], bh[2], bh[3]);
                    ldsm4(baddr + 32768, bl[0], bl[1], bl[2], bl[3]);
#pragma unroll
                    for (int mt = 0; mt < 2; mt++)
#pragma unroll
                        for (int j = 0; j < 2; j++) {
                            float* c = acc[hf][mt][np * 2 + j];
                            mma16816(c, ah[mt][0], ah[mt][1], ah[mt][2], ah[mt][3],
                                     bh[2 * j], bh[2 * j + 1]);
                            mma16816(c, ah[mt][0], ah[mt][1], ah[mt][2], ah[mt][3],
                                     bl[2 * j], bl[2 * j + 1]);
                            mma16816(c, al[mt][0], al[mt][1], al[mt][2], al[mt][3],
                                     bh[2 * j], bh[2 * j + 1]);
                        }
                }
        }

        // ---- self epilogue (hf=0): relu+bias, row-norm across 4 cg warps ----
        {
            float sums[2][2] = {{0.f, 0.f}, {0.f, 0.f}};
            float sqs[2][2] = {{0.f, 0.f}, {0.f, 0.f}};
#pragma unroll
            for (int mt = 0; mt < 2; mt++)
#pragma unroll
                for (int nf = 0; nf < 4; nf++) {
                    int col = ncol0 + nf * 8 + cq;
                    float ba = __ldg(b0 + col), bb2 = __ldg(b0 + col + 1);
                    float t0 = fmaxf(acc[0][mt][nf][0] + ba, 0.f);
                    float t1 = fmaxf(acc[0][mt][nf][1] + bb2, 0.f);
                    float t2 = fmaxf(acc[0][mt][nf][2] + ba, 0.f);
                    float t3 = fmaxf(acc[0][mt][nf][3] + bb2, 0.f);
                    sums[mt][0] += t0 + t1; sqs[mt][0] += t0 * t0 + t1 * t1;
                    sums[mt][1] += t2 + t3; sqs[mt][1] += t2 * t2 + t3 * t3;
                }
#pragma unroll
            for (int mk = 1; mk <= 2; mk <<= 1)
#pragma unroll
                for (int mt = 0; mt < 2; mt++)
#pragma unroll
                    for (int hh = 0; hh < 2; hh++) {
                        sums[mt][hh] += __shfl_xor_sync(0xffffffffu, sums[mt][hh], mk);
                        sqs[mt][hh]  += __shfl_xor_sync(0xffffffffu, sqs[mt][hh], mk);
                    }
            if ((lane & 3) == 0) {
#pragma unroll
                for (int mt = 0; mt < 2; mt++)
#pragma unroll
                    for (int hh = 0; hh < 2; hh++) {
                        int lr = mrow0 + mt * 16 + hh * 8 + rq;
                        ex[lr * 4 + cg] = make_float2(sums[mt][hh], sqs[mt][hh]);
                    }
            }
            __syncthreads();
            float meanv[2][2], rsv[2][2];
#pragma unroll
            for (int mt = 0; mt < 2; mt++)
#pragma unroll
                for (int hh = 0; hh < 2; hh++) {
                    int lr = mrow0 + mt * 16 + hh * 8 + rq;
                    float sum = 0.f, sq = 0.f;
#pragma unroll
                    for (int g = 0; g < 4; g++) {
                        float2 e = ex[lr * 4 + g];
                        sum += e.x; sq += e.y;
                    }
                    float mean = sum * (1.f / 128.f);
                    float var = fmaxf(sq * (1.f / 128.f) - mean * mean, 0.f);
                    meanv[mt][hh] = mean;
                    rsv[mt][hh] = rsqrtf(var + 1e-9f);
                }
#pragma unroll
            for (int mt = 0; mt < 2; mt++) {
                int r0g = row0 + mrow0 + mt * 16 + rq;
#pragma unroll
                for (int nf = 0; nf < 4; nf++) {
                    int col = ncol0 + nf * 8 + cq;
                    float ba = __ldg(b0 + col), bb2 = __ldg(b0 + col + 1);
                    float sa = __ldg(sc0 + col), sb2 = __ldg(sc0 + col + 1);
                    float oa = __ldg(off0 + col), ob = __ldg(off0 + col + 1);
                    if (r0g < n) {
                        float t0 = fmaxf(acc[0][mt][nf][0] + ba, 0.f);
                        float t1 = fmaxf(acc[0][mt][nf][1] + bb2, 0.f);
                        *reinterpret_cast<float2*>(&g_self[(size_t)r0g * 128 + col]) =
                            make_float2(sa * (t0 - meanv[mt][0]) * rsv[mt][0] + oa,
                                        sb2 * (t1 - meanv[mt][0]) * rsv[mt][0] + ob);
                    }
                    if (r0g + 8 < n) {
                        float t2 = fmaxf(acc[0][mt][nf][2] + ba, 0.f);
                        float t3 = fmaxf(acc[0][mt][nf][3] + bb2, 0.f);
                        *reinterpret_cast<float2*>(&g_self[(size_t)(r0g + 8) * 128 + col]) =
                            make_float2(sa * (t2 - meanv[mt][1]) * rsv[mt][1] + oa,
                                        sb2 * (t3 - meanv[mt][1]) * rsv[mt][1] + ob);
                    }
                }
            }
        }

        // ---- vw epilogue (hf=1): fp16 stores + attention dots (head = cg) --
        {
            float d0a[2][2] = {{0.f, 0.f}, {0.f, 0.f}};
            float d1a[2][2] = {{0.f, 0.f}, {0.f, 0.f}};
#pragma unroll
            for (int mt = 0; mt < 2; mt++) {
                int r0g = row0 + mrow0 + mt * 16 + rq;
#pragma unroll
                for (int nf = 0; nf < 4; nf++) {
                    int col = ncol0 + nf * 8 + cq;
                    float a00 = __ldg(att0 + col), a01 = __ldg(att0 + col + 1);
                    float a10 = __ldg(att1 + col), a11 = __ldg(att1 + col + 1);
                    float v0 = acc[1][mt][nf][0], v1 = acc[1][mt][nf][1];
                    float v2 = acc[1][mt][nf][2], v3 = acc[1][mt][nf][3];
                    if (r0g < n) {
                        __half2 p = __floats2half2_rn(v0, v1);
                        *reinterpret_cast<__half2*>(&g_vwh[(size_t)r0g * 128 + col]) = p;
                    }
                    if (r0g + 8 < n) {
                        __half2 p = __floats2half2_rn(v2, v3);
                        *reinterpret_cast<__half2*>(&g_vwh[(size_t)(r0g + 8) * 128 + col]) = p;
                    }
                    d0a[mt][0] += v0 * a00 + v1 * a01;
                    d0a[mt][1] += v2 * a00 + v3 * a01;
                    d1a[mt][0] += v0 * a10 + v1 * a11;
                    d1a[mt][1] += v2 * a10 + v3 * a11;
                }
            }
#pragma unroll
            for (int mk = 1; mk <= 2; mk <<= 1)
#pragma unroll
                for (int mt = 0; mt < 2; mt++)
#pragma unroll
                    for (int hh = 0; hh < 2; hh++) {
                        d0a[mt][hh] += __shfl_xor_sync(0xffffffffu, d0a[mt][hh], mk);
                        d1a[mt][hh] += __shfl_xor_sync(0xffffffffu, d1a[mt][hh], mk);
                    }
            if ((lane & 3) == 0) {
                float ab0 = __ldg(attb0 + cg);
                float ab1 = __ldg(attb1 + cg);
#pragma unroll
                for (int mt = 0; mt < 2; mt++)
#pragma unroll
                    for (int hh = 0; hh < 2; hh++) {
                        int rg = row0 + mrow0 + mt * 16 + hh * 8 + rq;
                        if (rg < n) {
                            g_a0[(size_t)rg * 4 + cg] = d0a[mt][hh] + ab0;
                            g_a1[(size_t)rg * 4 + cg] = d1a[mt][hh] + ab1;
                        }
                    }
            }
        }
        __syncthreads();   // protect A + ex before next tile overwrites
    }
}

// ---------------- kernel 2: full-degree histogram ----------------------------
__global__ __launch_bounds__(256) void hist_kernel(const int* __restrict__ rows, int e) {
    int i = blockIdx.x * 256 + threadIdx.x;
    if (i >= e) return;
    atomicAdd(&g_cnt[__ldg(rows + i)], 1);
}

// ---------------- kernel 3: single-pass decoupled-lookback scan -------------
__global__ __launch_bounds__(256) void scan_kernel(int n) {
    __shared__ int s_bid;
    __shared__ int s_wsum[8];
    __shared__ int s_prefix;
    int tid = threadIdx.x;
    int wid = tid >> 5;
    int lane = tid & 31;

    if (tid == 0) s_bid = atomicAdd(&g_ticket, 1);
    __syncthreads();
    int bid = s_bid;

    int i = bid * 256 + tid;
    int v = (i < n) ? g_cnt[i] : 0;

    int incl = v;
#pragma unroll
    for (int m = 1; m < 32; m <<= 1) {
        int x = __shfl_up_sync(0xffffffffu, incl, m);
        if (lane >= m) incl += x;
    }
    if (lane == 31) s_wsum[wid] = incl;
    __syncthreads();
    if (wid == 0 && lane < 8) {
        int w = s_wsum[lane];
#pragma unroll
        for (int m = 1; m < 8; m <<= 1) {
            int x = __shfl_up_sync(0xffu, w, m);
            if (lane >= m) w += x;
        }
        s_wsum[lane] = w;
    }
    __syncthreads();
    int blocksum = s_wsum[7];
    if (wid > 0) incl += s_wsum[wid - 1];

    if (tid == 0) {
        unsigned int tag = (bid == 0) ? ((2u << 30) | (unsigned int)blocksum)
                                      : ((1u << 30) | (unsigned int)blocksum);
        g_state[bid] = tag;
        __threadfence();
    }

    if (wid == 0) {
        int prefix = 0;
        if (bid > 0) {
            int look = bid - 1;
            while (true) {
                int idx2 = look - lane;
                unsigned int st;
                if (idx2 < 0) {
                    st = (2u << 30);
                } else {
                    do { st = g_state[idx2]; } while ((st >> 30) == 0u);
                }
                unsigned int status = st >> 30;
                int val = (int)(st & 0x3FFFFFFFu);
                unsigned int ball = __ballot_sync(0xffffffffu, status >= 2u);
                if (ball) {
                    int first = __ffs(ball) - 1;
                    int contrib = (lane <= first) ? val : 0;
#pragma unroll
                    for (int m = 16; m > 0; m >>= 1)
                        contrib += __shfl_xor_sync(0xffffffffu, contrib, m);
                    prefix += contrib;
                    break;
                } else {
                    int contrib = val;
#pragma unroll
                    for (int m = 16; m > 0; m >>= 1)
                        contrib += __shfl_xor_sync(0xffffffffu, contrib, m);
                    prefix += contrib;
                    look -= 32;
                }
            }
            if (lane == 0) {
                g_state[bid] = (2u << 30) | (unsigned int)(prefix + blocksum);
                __threadfence();
            }
        }
        if (lane == 0) s_prefix = prefix;
    }
    __syncthreads();

    if (i < n) {
        int start = s_prefix + incl - v;
        g_start[i] = start;
        g_cursor[i] = start;
    }
}

// ---------------- kernel 4: compute weights, filter, compact ----------------
__global__ __launch_bounds__(256) void scatter_kernel(const float* __restrict__ vals,
                                                      const int* __restrict__ rows,
                                                      const int* __restrict__ cols, int e) {
    int i = blockIdx.x * 256 + threadIdx.x;
    if (i >= e) return;
    int r = __ldg(rows + i);
    int c = __ldg(cols + i);
    float val = __ldg(vals + i);
    float4 ar = __ldg(reinterpret_cast<const float4*>(&g_a0[(size_t)r * 4]));
    float4 ac = __ldg(reinterpret_cast<const float4*>(&g_a1[(size_t)c * 4]));
    float w0 = val * fmaxf(ar.x + ac.x, 0.f);
    float w1 = val * fmaxf(ar.y + ac.y, 0.f);
    float w2 = val * fmaxf(ar.z + ac.z, 0.f);
    float w3 = val * fmaxf(ar.w + ac.w, 0.f);
    if (w0 + w1 + w2 + w3 > 0.f) {
        int pos = atomicAdd(&g_cursor[r], 1);
        g_ecol[pos] = (unsigned int)c;
        __half2 p0 = __floats2half2_rn(w0, w1);
        __half2 p1 = __floats2half2_rn(w2, w3);
        uint2 pk;
        pk.x = *reinterpret_cast<uint32_t*>(&p0);
        pk.y = *reinterpret_cast<uint32_t*>(&p1);
        *reinterpret_cast<uint2*>(&g_ewh[(size_t)pos * 4]) = pk;
    }
}

// ---------------- kernel 5: per-row aggregation + fused epilogue ------------
__global__ __launch_bounds__(256) void agg_kernel(const float* __restrict__ b1,
                                                  const float* __restrict__ off1,
                                                  const float* __restrict__ sc1,
                                                  float* __restrict__ out, int n) {
    int r = (blockIdx.x << 3) + (threadIdx.x >> 5);
    if (r >= n) return;
    int lane = threadIdx.x & 31;
    int j = lane << 2;
    int h = lane >> 3;

    int start = g_start[r];
    int deg = g_cursor[r] - start;

    float4 acc = make_float4(0.f, 0.f, 0.f, 0.f);

    auto gather = [&](unsigned int c, float w) {
        uint2 pk = __ldg(reinterpret_cast<const uint2*>(&g_vwh[(size_t)c * 128 + j]));
        float2 v0 = __half22float2(*reinterpret_cast<__half2*>(&pk.x));
        float2 v1 = __half22float2(*reinterpret_cast<__half2*>(&pk.y));
        acc.x += w * v0.x;
        acc.y += w * v0.y;
        acc.z += w * v1.x;
        acc.w += w * v1.y;
    };

    int i = 0;
    for (; i + 4 <= deg; i += 4) {
        unsigned int c0 = __ldg(&g_ecol[start + i + 0]);
        unsigned int c1 = __ldg(&g_ecol[start + i + 1]);
        unsigned int c2 = __ldg(&g_ecol[start + i + 2]);
        unsigned int c3 = __ldg(&g_ecol[start + i + 3]);
        float w0 = __half2float(__ldg(&g_ewh[(size_t)(start + i + 0) * 4 + h]));
        float w1 = __half2float(__ldg(&g_ewh[(size_t)(start + i + 1) * 4 + h]));
        float w2 = __half2float(__ldg(&g_ewh[(size_t)(start + i + 2) * 4 + h]));
        float w3 = __half2float(__ldg(&g_ewh[(size_t)(start + i + 3) * 4 + h]));
        if (w0 > 0.f) gather(c0, w0);
        if (w1 > 0.f) gather(c1, w1);
        if (w2 > 0.f) gather(c2, w2);
        if (w3 > 0.f) gather(c3, w3);
    }
    for (; i < deg; i++) {
        unsigned int c = __ldg(&g_ecol[start + i]);
        float w = __half2float(__ldg(&g_ewh[(size_t)(start + i) * 4 + h]));
        if (w > 0.f) gather(c, w);
    }

    float t0 = fmaxf(acc.x, 0.f) + b1[j + 0];
    float t1 = fmaxf(acc.y, 0.f) + b1[j + 1];
    float t2 = fmaxf(acc.z, 0.f) + b1[j + 2];
    float t3 = fmaxf(acc.w, 0.f) + b1[j + 3];
    float sum = t0 + t1 + t2 + t3;
    float sq = t0 * t0 + t1 * t1 + t2 * t2 + t3 * t3;
#pragma unroll
    for (int m = 16; m > 0; m >>= 1) {
        sum += __shfl_xor_sync(0xffffffffu, sum, m);
        sq  += __shfl_xor_sync(0xffffffffu, sq, m);
    }
    float mean = sum * (1.f / 128.f);
    float var = fmaxf(sq * (1.f / 128.f) - mean * mean, 0.f);
    float rs = rsqrtf(var + 1e-9f);
    float4 s = *reinterpret_cast<const float4*>(&g_self[(size_t)r * 128 + j]);
    float4 o;
    o.x = sc1[j + 0] * (t0 - mean) * rs + off1[j + 0] + s.x;
    o.y = sc1[j + 1] * (t1 - mean) * rs + off1[j + 1] + s.y;
    o.z = sc1[j + 2] * (t2 - mean) * rs + off1[j + 2] + s.z;
    o.w = sc1[j + 3] * (t3 - mean) * rs + off1[j + 3] + s.w;
    *reinterpret_cast<float4*>(&out[(size_t)r * 128 + j]) = o;
}

// ---------------- launch ----------------------------------------------------
extern "C" void kernel_launch(void* const* d_in, const int* in_sizes, int n_in,
                              void* d_out, int out_size) {
    const float* vecs     = (const float*)d_in[0];
    const float* adj_vals = (const float*)d_in[1];
    const float* W0       = (const float*)d_in[2];
    const float* b0       = (const float*)d_in[3];
    const float* W1       = (const float*)d_in[4];
    const float* b1       = (const float*)d_in[5];
    const float* att0     = (const float*)d_in[6];
    const float* att1     = (const float*)d_in[7];
    const float* attb0    = (const float*)d_in[8];
    const float* attb1    = (const float*)d_in[9];
    const float* off0     = (const float*)d_in[10];
    const float* sc0      = (const float*)d_in[11];
    const float* off1     = (const float*)d_in[12];
    const float* sc1      = (const float*)d_in[13];
    const int*   rows     = (const int*)d_in[14];
    const int*   cols     = (const int*)d_in[15];

    int n = in_sizes[0] / 128;
    int e = in_sizes[1];
    float* out = (float*)d_out;

    int nb = (n + 255) / 256;
    int nbp = nb < 128 ? 128 : nb;
    int ntiles = (n + 127) / 128;
    int grid = ntiles < 152 ? ntiles : 152;

    static cudaStream_t s2 = nullptr;
    static cudaEvent_t ev_fork = nullptr, ev_join = nullptr;
    static int smem_set = 0;
    if (!smem_set) {
        cudaFuncSetAttribute(gemm_tc_kernel, cudaFuncAttributeMaxDynamicSharedMemorySize,
                             SMEM_TOTAL);
        cudaStreamCreateWithFlags(&s2, cudaStreamNonBlocking);
        cudaEventCreateWithFlags(&ev_fork, cudaEventDisableTiming);
        cudaEventCreateWithFlags(&ev_join, cudaEventDisableTiming);
        smem_set = 1;
    }

    pack_kernel<<<nbp, 256>>>(W0, W1, n);
    cudaEventRecord(ev_fork, 0);
    cudaStreamWaitEvent(s2, ev_fork, 0);

    hist_kernel<<<(e + 255) / 256, 256, 0, s2>>>(rows, e);
    scan_kernel<<<nb, 256, 0, s2>>>(n);
    cudaEventRecord(ev_join, s2);

    gemm_tc_kernel<<<grid, 512, SMEM_TOTAL>>>(vecs, b0, att0, att1, attb0, attb1,
                                              off0, sc0, n, ntiles);
    cudaStreamWaitEvent(0, ev_join, 0);

    scatter_kernel<<<(e + 255) / 256, 256>>>(adj_vals, rows, cols, e);
    agg_kernel<<<(n + 7) / 8, 256>>>(b1, off1, sc1, out, n);
}

// round 10
// speedup vs baseline: 1.0640x; 1.0640x over previous
#include <cuda_runtime.h>
#include <cuda_bf16.h>
#include <cuda_fp16.h>
#include <cstdint>

#define MAXN 100000
#define MAXE 1600000

// ---------------- scratch (device globals; no allocation allowed) ----------
// B packed: [half(2)][split(2)][kchunk(8)][n(128)][16 bf16] = 131072 bytes
__device__ __align__(16) uint8_t g_Bpk[131072];
__device__ __align__(16) float  g_self[MAXN * 128];
__device__ __align__(16) __half g_vwh[MAXN * 128];     // fp16 vw for edge gather
__device__ __align__(16) float  g_a0[MAXN * 4];
__device__ __align__(16) float  g_a1[MAXN * 4];
__device__ int   g_cnt[MAXN];                          // FULL degree per dest row
__device__ int   g_start[MAXN];
__device__ int   g_cursor[MAXN];
__device__ int   g_ticket;                             // scan tile ticket
__device__ volatile unsigned int g_state[512];         // (status<<30)|sum
__device__ __align__(8) uint2 g_erec[MAXE];            // CSR records {col, val bits}

// ---------------- helpers ---------------------------------------------------
__device__ __forceinline__ uint32_t smem_u32(const void* p) {
    uint32_t a;
    asm("{ .reg .u64 t; cvta.to.shared.u64 t, %1; cvt.u32.u64 %0, t; }" : "=r"(a) : "l"(p));
    return a;
}
__device__ __forceinline__ void ldsm4(uint32_t addr, uint32_t& r0, uint32_t& r1,
                                      uint32_t& r2, uint32_t& r3) {
    asm volatile("ldmatrix.sync.aligned.m8n8.x4.shared.b16 {%0,%1,%2,%3}, [%4];"
                 : "=r"(r0), "=r"(r1), "=r"(r2), "=r"(r3) : "r"(addr));
}
__device__ __forceinline__ void mma16816(float* c, uint32_t a0, uint32_t a1, uint32_t a2,
                                         uint32_t a3, uint32_t b0, uint32_t b1) {
    asm volatile(
        "mma.sync.aligned.m16n8k16.row.col.f32.bf16.bf16.f32 "
        "{%0,%1,%2,%3},{%4,%5,%6,%7},{%8,%9},{%0,%1,%2,%3};"
        : "+f"(c[0]), "+f"(c[1]), "+f"(c[2]), "+f"(c[3])
        : "r"(a0), "r"(a1), "r"(a2), "r"(a3), "r"(b0), "r"(b1));
}

// SMEM: B resident [hf(2)][sp(2)][kc(8)][128][32B] = 131072
//       A [sp(2)][kc(8)][row(128)][32B]            = 65536
//       ex row exchange 128 rows x 2 halves float2 = 2048
#define SMEM_B 0
#define SMEM_A 131072
#define SMEM_EX (131072 + 65536)
#define SMEM_TOTAL (131072 + 65536 + 2048)

// ---------------- kernel 0: pack B (bf16 hi/lo) + zero cnt/scan state ------
__global__ __launch_bounds__(256) void pack_kernel(const float* __restrict__ W0,
                                                   const float* __restrict__ W1, int n) {
    int idx = blockIdx.x * 256 + threadIdx.x;
    if (idx < 32768) {
        int k = idx >> 8;          // 0..127
        int c = idx & 255;         // 0..255 global output col
        float v;
        if (c < 128) {
            v = W0[k * 128 + c];
        } else {
            int j = c - 128;
            int h = j >> 5;
            int k2 = j & 31;
            v = W1[(h * 128 + k) * 32 + k2];
        }
        __nv_bfloat16 hi = __float2bfloat16_rn(v);
        __nv_bfloat16 lo = __float2bfloat16_rn(v - __bfloat162float(hi));
        int hf = c >> 7;
        int nn = c & 127;
        int kc = k >> 4;
        int kk = k & 15;
        int base = ((hf * 2 + 0) * 8 + kc) * 4096 + nn * 32 + kk * 2;
        *reinterpret_cast<__nv_bfloat16*>(g_Bpk + base) = hi;
        *reinterpret_cast<__nv_bfloat16*>(g_Bpk + base + 32768) = lo;   // sp stride = 8*4096
    }
    if (idx < n) g_cnt[idx] = 0;
    if (idx < 512) g_state[idx] = 0;
    if (idx == 0) g_ticket = 0;
}

// ---------------- kernel 1: persistent mma.sync GEMM, fragment epilogues ----
__global__ __launch_bounds__(256, 1) void gemm_tc_kernel(
    const float* __restrict__ vecs, const float* __restrict__ b0,
    const float* __restrict__ att0, const float* __restrict__ att1,
    const float* __restrict__ attb0, const float* __restrict__ attb1,
    const float* __restrict__ off0, const float* __restrict__ sc0, int n, int ntiles) {
    extern __shared__ __align__(1024) char smem[];
    uint32_t sb = smem_u32(smem);
    float2* ex = reinterpret_cast<float2*>(smem + SMEM_EX);
    int tid = threadIdx.x;
    int wid = tid >> 5;
    int lane = tid & 31;

    int mrow0 = (wid & 3) * 32;
    int nbase = (wid >> 2) * 64;
    int rq = lane >> 2;          // row-in-8 selector
    int cq = 2 * (lane & 3);     // col pair selector

    int lt = lane >> 3;
    int l7 = lane & 7;
    int alane = ((lt & 1) * 8 + l7) * 32 + (lt >> 1) * 16;
    int blane = ((lt >> 1) * 8 + l7) * 32 + (lt & 1) * 16;

    // ---- load full B (131072 B) once, resident for kernel lifetime ----
    {
        const uint4* src = reinterpret_cast<const uint4*>(g_Bpk);
        uint4* dst = reinterpret_cast<uint4*>(smem + SMEM_B);
#pragma unroll
        for (int i = 0; i < 32; i++) dst[tid + i * 256] = __ldg(&src[tid + i * 256]);
    }
    __syncthreads();

    float acc[2][8][4];

    auto compute_pass = [&](int hf) {
#pragma unroll
        for (int mt = 0; mt < 2; mt++)
#pragma unroll
            for (int nf = 0; nf < 8; nf++)
#pragma unroll
                for (int q = 0; q < 4; q++) acc[mt][nf][q] = 0.f;
        uint32_t Bbase = sb + SMEM_B + hf * 65536;
        uint32_t Abase = sb + SMEM_A;
#pragma unroll
        for (int kc = 0; kc < 8; kc++) {
            uint32_t ah[2][4], al[2][4];
#pragma unroll
            for (int mt = 0; mt < 2; mt++) {
                uint32_t aaddr = Abase + kc * 4096 + (mrow0 + mt * 16) * 32 + alane;
                ldsm4(aaddr, ah[mt][0], ah[mt][1], ah[mt][2], ah[mt][3]);
                ldsm4(aaddr + 32768, al[mt][0], al[mt][1], al[mt][2], al[mt][3]);
            }
#pragma unroll
            for (int np = 0; np < 4; np++) {
                uint32_t bh[4], bl[4];
                uint32_t baddr = Bbase + kc * 4096 + (nbase + np * 16) * 32 + blane;
                ldsm4(baddr, bh[0], bh[1], bh[2], bh[3]);
                ldsm4(baddr + 32768, bl[0], bl[1], bl[2], bl[3]);
#pragma unroll
                for (int mt = 0; mt < 2; mt++)
#pragma unroll
                    for (int j = 0; j < 2; j++) {
                        float* c = acc[mt][np * 2 + j];
                        mma16816(c, ah[mt][0], ah[mt][1], ah[mt][2], ah[mt][3],
                                 bh[2 * j], bh[2 * j + 1]);
                        mma16816(c, ah[mt][0], ah[mt][1], ah[mt][2], ah[mt][3],
                                 bl[2 * j], bl[2 * j + 1]);
                        mma16816(c, al[mt][0], al[mt][1], al[mt][2], al[mt][3],
                                 bh[2 * j], bh[2 * j + 1]);
                    }
            }
        }
    };

    for (int tile = blockIdx.x; tile < ntiles; tile += gridDim.x) {
        int row0 = tile * 128;

        // ---- load A tile: fp32 -> bf16 hi/lo, [sp][kc][row][32B] ----
#pragma unroll
        for (int it = 0; it < 16; it++) {
            int t = it * 256 + tid;
            int r = t >> 5;
            int q = t & 31;
            float4 v = make_float4(0.f, 0.f, 0.f, 0.f);
            int gr = row0 + r;
            if (gr < n) v = __ldg(reinterpret_cast<const float4*>(vecs + (size_t)gr * 128 + q * 4));
            __nv_bfloat16 h0 = __float2bfloat16_rn(v.x), h1 = __float2bfloat16_rn(v.y);
            __nv_bfloat16 h2 = __float2bfloat16_rn(v.z), h3 = __float2bfloat16_rn(v.w);
            __nv_bfloat16 l0 = __float2bfloat16_rn(v.x - __bfloat162float(h0));
            __nv_bfloat16 l1 = __float2bfloat16_rn(v.y - __bfloat162float(h1));
            __nv_bfloat16 l2 = __float2bfloat16_rn(v.z - __bfloat162float(h2));
            __nv_bfloat16 l3 = __float2bfloat16_rn(v.w - __bfloat162float(h3));
            uint2 hv, lv;
            hv.x = ((uint32_t)__bfloat16_as_ushort(h1) << 16) | __bfloat16_as_ushort(h0);
            hv.y = ((uint32_t)__bfloat16_as_ushort(h3) << 16) | __bfloat16_as_ushort(h2);
            lv.x = ((uint32_t)__bfloat16_as_ushort(l1) << 16) | __bfloat16_as_ushort(l0);
            lv.y = ((uint32_t)__bfloat16_as_ushort(l3) << 16) | __bfloat16_as_ushort(l2);
            int kc = q >> 2;
            int kq = q & 3;
            int off = kc * 4096 + r * 32 + kq * 8;
            *reinterpret_cast<uint2*>(smem + SMEM_A + off) = hv;
            *reinterpret_cast<uint2*>(smem + SMEM_A + 32768 + off) = lv;
        }
        __syncthreads();

        // ===== pass 0: self path (cols 0..127) =====
        compute_pass(0);

        // ---- self epilogue from fragments ----
        {
            float sums[2][2] = {{0.f, 0.f}, {0.f, 0.f}};
            float sqs[2][2] = {{0.f, 0.f}, {0.f, 0.f}};
#pragma unroll
            for (int mt = 0; mt < 2; mt++)
#pragma unroll
                for (int nf = 0; nf < 8; nf++) {
                    int col = nbase + nf * 8 + cq;
                    float ba = __ldg(b0 + col), bb2 = __ldg(b0 + col + 1);
                    float t0 = fmaxf(acc[mt][nf][0] + ba, 0.f);
                    float t1 = fmaxf(acc[mt][nf][1] + bb2, 0.f);
                    float t2 = fmaxf(acc[mt][nf][2] + ba, 0.f);
                    float t3 = fmaxf(acc[mt][nf][3] + bb2, 0.f);
                    sums[mt][0] += t0 + t1; sqs[mt][0] += t0 * t0 + t1 * t1;
                    sums[mt][1] += t2 + t3; sqs[mt][1] += t2 * t2 + t3 * t3;
                }
#pragma unroll
            for (int mk = 1; mk <= 2; mk <<= 1)
#pragma unroll
                for (int mt = 0; mt < 2; mt++)
#pragma unroll
                    for (int hh = 0; hh < 2; hh++) {
                        sums[mt][hh] += __shfl_xor_sync(0xffffffffu, sums[mt][hh], mk);
                        sqs[mt][hh]  += __shfl_xor_sync(0xffffffffu, sqs[mt][hh], mk);
                    }
            int wh = wid >> 2;
            if ((lane & 3) == 0) {
#pragma unroll
                for (int mt = 0; mt < 2; mt++)
#pragma unroll
                    for (int hh = 0; hh < 2; hh++) {
                        int lr = mrow0 + mt * 16 + hh * 8 + rq;
                        ex[lr * 2 + wh] = make_float2(sums[mt][hh], sqs[mt][hh]);
                    }
            }
            __syncthreads();
            float meanv[2][2], rsv[2][2];
#pragma unroll
            for (int mt = 0; mt < 2; mt++)
#pragma unroll
                for (int hh = 0; hh < 2; hh++) {
                    int lr = mrow0 + mt * 16 + hh * 8 + rq;
                    float2 e0 = ex[lr * 2 + 0], e1 = ex[lr * 2 + 1];
                    float sum = e0.x + e1.x, sq = e0.y + e1.y;
                    float mean = sum * (1.f / 128.f);
                    float var = fmaxf(sq * (1.f / 128.f) - mean * mean, 0.f);
                    meanv[mt][hh] = mean;
                    rsv[mt][hh] = rsqrtf(var + 1e-9f);
                }
#pragma unroll
            for (int mt = 0; mt < 2; mt++) {
                int r0g = row0 + mrow0 + mt * 16 + rq;
#pragma unroll
                for (int nf = 0; nf < 8; nf++) {
                    int col = nbase + nf * 8 + cq;
                    float ba = __ldg(b0 + col), bb2 = __ldg(b0 + col + 1);
                    float sa = __ldg(sc0 + col), sb2 = __ldg(sc0 + col + 1);
                    float oa = __ldg(off0 + col), ob = __ldg(off0 + col + 1);
                    if (r0g < n) {
                        float t0 = fmaxf(acc[mt][nf][0] + ba, 0.f);
                        float t1 = fmaxf(acc[mt][nf][1] + bb2, 0.f);
                        *reinterpret_cast<float2*>(&g_self[(size_t)r0g * 128 + col]) =
                            make_float2(sa * (t0 - meanv[mt][0]) * rsv[mt][0] + oa,
                                        sb2 * (t1 - meanv[mt][0]) * rsv[mt][0] + ob);
                    }
                    if (r0g + 8 < n) {
                        float t2 = fmaxf(acc[mt][nf][2] + ba, 0.f);
                        float t3 = fmaxf(acc[mt][nf][3] + bb2, 0.f);
                        *reinterpret_cast<float2*>(&g_self[(size_t)(r0g + 8) * 128 + col]) =
                            make_float2(sa * (t2 - meanv[mt][1]) * rsv[mt][1] + oa,
                                        sb2 * (t3 - meanv[mt][1]) * rsv[mt][1] + ob);
                    }
                }
            }
        }

        // ===== pass 1: vw path (cols 128..255) =====
        compute_pass(1);

        // ---- vw epilogue: fp16 stores + attention dots from fragments ----
        {
            int h0 = nbase >> 5;
            float d0p[2][2][2], d1p[2][2][2];
#pragma unroll
            for (int mt = 0; mt < 2; mt++)
#pragma unroll
                for (int hh = 0; hh < 2; hh++)
#pragma unroll
                    for (int hs = 0; hs < 2; hs++) { d0p[mt][hh][hs] = 0.f; d1p[mt][hh][hs] = 0.f; }
#pragma unroll
            for (int mt = 0; mt < 2; mt++) {
                int r0g = row0 + mrow0 + mt * 16 + rq;
#pragma unroll
                for (int nf = 0; nf < 8; nf++) {
                    int col = nbase + nf * 8 + cq;
                    float a00 = __ldg(att0 + col), a01 = __ldg(att0 + col + 1);
                    float a10 = __ldg(att1 + col), a11 = __ldg(att1 + col + 1);
                    float v0 = acc[mt][nf][0], v1 = acc[mt][nf][1];
                    float v2 = acc[mt][nf][2], v3 = acc[mt][nf][3];
                    if (r0g < n) {
                        __half2 p = __floats2half2_rn(v0, v1);
                        *reinterpret_cast<__half2*>(&g_vwh[(size_t)r0g * 128 + col]) = p;
                    }
                    if (r0g + 8 < n) {
                        __half2 p = __floats2half2_rn(v2, v3);
                        *reinterpret_cast<__half2*>(&g_vwh[(size_t)(r0g + 8) * 128 + col]) = p;
                    }
                    int hs = nf >> 2;
                    d0p[mt][0][hs] += v0 * a00 + v1 * a01;
                    d0p[mt][1][hs] += v2 * a00 + v3 * a01;
                    d1p[mt][0][hs] += v0 * a10 + v1 * a11;
                    d1p[mt][1][hs] += v2 * a10 + v3 * a11;
                }
            }
#pragma unroll
            for (int mk = 1; mk <= 2; mk <<= 1)
#pragma unroll
                for (int mt = 0; mt < 2; mt++)
#pragma unroll
                    for (int hh = 0; hh < 2; hh++)
#pragma unroll
                        for (int hs = 0; hs < 2; hs++) {
                            d0p[mt][hh][hs] += __shfl_xor_sync(0xffffffffu, d0p[mt][hh][hs], mk);
                            d1p[mt][hh][hs] += __shfl_xor_sync(0xffffffffu, d1p[mt][hh][hs], mk);
                        }
            if ((lane & 3) == 0) {
#pragma unroll
                for (int mt = 0; mt < 2; mt++)
#pragma unroll
                    for (int hh = 0; hh < 2; hh++) {
                        int rg = row0 + mrow0 + mt * 16 + hh * 8 + rq;
                        if (rg < n) {
#pragma unroll
                            for (int hs = 0; hs < 2; hs++) {
                                g_a0[(size_t)rg * 4 + h0 + hs] =
                                    d0p[mt][hh][hs] + __ldg(attb0 + h0 + hs);
                                g_a1[(size_t)rg * 4 + h0 + hs] =
                                    d1p[mt][hh][hs] + __ldg(attb1 + h0 + hs);
                            }
                        }
                    }
            }
        }
        __syncthreads();   // protect A + ex before next tile overwrites
    }
}

// ---------------- kernel 2: full-degree histogram ----------------------------
__global__ __launch_bounds__(256) void hist_kernel(const int* __restrict__ rows, int e) {
    int i = blockIdx.x * 256 + threadIdx.x;
    if (i >= e) return;
    atomicAdd(&g_cnt[__ldg(rows + i)], 1);
}

// ---------------- kernel 3: single-pass decoupled-lookback scan -------------
__global__ __launch_bounds__(256) void scan_kernel(int n) {
    __shared__ int s_bid;
    __shared__ int s_wsum[8];
    __shared__ int s_prefix;
    int tid = threadIdx.x;
    int wid = tid >> 5;
    int lane = tid & 31;

    if (tid == 0) s_bid = atomicAdd(&g_ticket, 1);
    __syncthreads();
    int bid = s_bid;

    int i = bid * 256 + tid;
    int v = (i < n) ? g_cnt[i] : 0;

    int incl = v;
#pragma unroll
    for (int m = 1; m < 32; m <<= 1) {
        int x = __shfl_up_sync(0xffffffffu, incl, m);
        if (lane >= m) incl += x;
    }
    if (lane == 31) s_wsum[wid] = incl;
    __syncthreads();
    if (wid == 0 && lane < 8) {
        int w = s_wsum[lane];
#pragma unroll
        for (int m = 1; m < 8; m <<= 1) {
            int x = __shfl_up_sync(0xffu, w, m);
            if (lane >= m) w += x;
        }
        s_wsum[lane] = w;
    }
    __syncthreads();
    int blocksum = s_wsum[7];
    if (wid > 0) incl += s_wsum[wid - 1];

    if (tid == 0) {
        unsigned int tag = (bid == 0) ? ((2u << 30) | (unsigned int)blocksum)
                                      : ((1u << 30) | (unsigned int)blocksum);
        g_state[bid] = tag;
        __threadfence();
    }

    if (wid == 0) {
        int prefix = 0;
        if (bid > 0) {
            int look = bid - 1;
            while (true) {
                int idx2 = look - lane;
                unsigned int st;
                if (idx2 < 0) {
                    st = (2u << 30);
                } else {
                    do { st = g_state[idx2]; } while ((st >> 30) == 0u);
                }
                unsigned int status = st >> 30;
                int val = (int)(st & 0x3FFFFFFFu);
                unsigned int ball = __ballot_sync(0xffffffffu, status >= 2u);
                if (ball) {
                    int first = __ffs(ball) - 1;
                    int contrib = (lane <= first) ? val : 0;
#pragma unroll
                    for (int m = 16; m > 0; m >>= 1)
                        contrib += __shfl_xor_sync(0xffffffffu, contrib, m);
                    prefix += contrib;
                    break;
                } else {
                    int contrib = val;
#pragma unroll
                    for (int m = 16; m > 0; m >>= 1)
                        contrib += __shfl_xor_sync(0xffffffffu, contrib, m);
                    prefix += contrib;
                    look -= 32;
                }
            }
            if (lane == 0) {
                g_state[bid] = (2u << 30) | (unsigned int)(prefix + blocksum);
                __threadfence();
            }
        }
        if (lane == 0) s_prefix = prefix;
    }
    __syncthreads();

    if (i < n) {
        int start = s_prefix + incl - v;
        g_start[i] = start;
        g_cursor[i] = start;
    }
}

// ---------------- kernel 4: CSR scatter (no attention dependency!) ----------
__global__ __launch_bounds__(256) void scatter_kernel(const float* __restrict__ vals,
                                                      const int* __restrict__ rows,
                                                      const int* __restrict__ cols, int e) {
    int i = blockIdx.x * 256 + threadIdx.x;
    if (i >= e) return;
    int r = __ldg(rows + i);
    int c = __ldg(cols + i);
    float val = __ldg(vals + i);
    int pos = atomicAdd(&g_cursor[r], 1);
    g_erec[pos] = make_uint2((unsigned int)c, __float_as_uint(val));
}

// ---------------- kernel 5: per-row aggregation + on-the-fly weights --------
__global__ __launch_bounds__(256) void agg_kernel(const float* __restrict__ b1,
                                                  const float* __restrict__ off1,
                                                  const float* __restrict__ sc1,
                                                  float* __restrict__ out, int n) {
    int r = (blockIdx.x << 3) + (threadIdx.x >> 5);
    if (r >= n) return;
    int lane = threadIdx.x & 31;
    int j = lane << 2;
    int h = lane >> 3;

    int start = g_start[r];
    int deg = g_cnt[r];
    float a0h = __ldg(&g_a0[(size_t)r * 4 + h]);   // warp covers 4 heads; per-lane head value

    float4 acc = make_float4(0.f, 0.f, 0.f, 0.f);

    auto process = [&](uint2 rec) {
        unsigned int c = rec.x;
        float val = __uint_as_float(rec.y);
        float a1h = __ldg(&g_a1[(size_t)c * 4 + h]);
        float w = val * fmaxf(a0h + a1h, 0.f);
        if (w > 0.f) {
            uint2 pk = __ldg(reinterpret_cast<const uint2*>(&g_vwh[(size_t)c * 128 + j]));
            float2 v0 = __half22float2(*reinterpret_cast<__half2*>(&pk.x));
            float2 v1 = __half22float2(*reinterpret_cast<__half2*>(&pk.y));
            acc.x += w * v0.x;
            acc.y += w * v0.y;
            acc.z += w * v1.x;
            acc.w += w * v1.y;
        }
    };

    int i = 0;
    for (; i + 4 <= deg; i += 4) {
        uint2 r0 = __ldg(&g_erec[start + i + 0]);
        uint2 r1 = __ldg(&g_erec[start + i + 1]);
        uint2 r2 = __ldg(&g_erec[start + i + 2]);
        uint2 r3 = __ldg(&g_erec[start + i + 3]);
        process(r0);
        process(r1);
        process(r2);
        process(r3);
    }
    for (; i < deg; i++) process(__ldg(&g_erec[start + i]));

    float t0 = fmaxf(acc.x, 0.f) + b1[j + 0];
    float t1 = fmaxf(acc.y, 0.f) + b1[j + 1];
    float t2 = fmaxf(acc.z, 0.f) + b1[j + 2];
    float t3 = fmaxf(acc.w, 0.f) + b1[j + 3];
    float sum = t0 + t1 + t2 + t3;
    float sq = t0 * t0 + t1 * t1 + t2 * t2 + t3 * t3;
#pragma unroll
    for (int m = 16; m > 0; m >>= 1) {
        sum += __shfl_xor_sync(0xffffffffu, sum, m);
        sq  += __shfl_xor_sync(0xffffffffu, sq, m);
    }
    float mean = sum * (1.f / 128.f);
    float var = fmaxf(sq * (1.f / 128.f) - mean * mean, 0.f);
    float rs = rsqrtf(var + 1e-9f);
    float4 s = *reinterpret_cast<const float4*>(&g_self[(size_t)r * 128 + j]);
    float4 o;
    o.x = sc1[j + 0] * (t0 - mean) * rs + off1[j + 0] + s.x;
    o.y = sc1[j + 1] * (t1 - mean) * rs + off1[j + 1] + s.y;
    o.z = sc1[j + 2] * (t2 - mean) * rs + off1[j + 2] + s.z;
    o.w = sc1[j + 3] * (t3 - mean) * rs + off1[j + 3] + s.w;
    *reinterpret_cast<float4*>(&out[(size_t)r * 128 + j]) = o;
}

// ---------------- launch ----------------------------------------------------
extern "C" void kernel_launch(void* const* d_in, const int* in_sizes, int n_in,
                              void* d_out, int out_size) {
    const float* vecs     = (const float*)d_in[0];
    const float* adj_vals = (const float*)d_in[1];
    const float* W0       = (const float*)d_in[2];
    const float* b0       = (const float*)d_in[3];
    const float* W1       = (const float*)d_in[4];
    const float* b1       = (const float*)d_in[5];
    const float* att0     = (const float*)d_in[6];
    const float* att1     = (const float*)d_in[7];
    const float* attb0    = (const float*)d_in[8];
    const float* attb1    = (const float*)d_in[9];
    const float* off0     = (const float*)d_in[10];
    const float* sc0      = (const float*)d_in[11];
    const float* off1     = (const float*)d_in[12];
    const float* sc1      = (const float*)d_in[13];
    const int*   rows     = (const int*)d_in[14];
    const int*   cols     = (const int*)d_in[15];

    int n = in_sizes[0] / 128;
    int e = in_sizes[1];
    float* out = (float*)d_out;

    int nb = (n + 255) / 256;
    int nbp = nb < 128 ? 128 : nb;
    int ntiles = (n + 127) / 128;
    int grid = ntiles < 152 ? ntiles : 152;

    static cudaStream_t s2 = nullptr;
    static cudaEvent_t ev_fork = nullptr, ev_join = nullptr;
    static int smem_set = 0;
    if (!smem_set) {
        cudaFuncSetAttribute(gemm_tc_kernel, cudaFuncAttributeMaxDynamicSharedMemorySize,
                             SMEM_TOTAL);
        cudaStreamCreateWithFlags(&s2, cudaStreamNonBlocking);
        cudaEventCreateWithFlags(&ev_fork, cudaEventDisableTiming);
        cudaEventCreateWithFlags(&ev_join, cudaEventDisableTiming);
        smem_set = 1;
    }

    pack_kernel<<<nbp, 256>>>(W0, W1, n);
    cudaEventRecord(ev_fork, 0);
    cudaStreamWaitEvent(s2, ev_fork, 0);

    // side stream: entire CSR build, independent of the GEMM
    hist_kernel<<<(e + 255) / 256, 256, 0, s2>>>(rows, e);
    scan_kernel<<<nb, 256, 0, s2>>>(n);
    scatter_kernel<<<(e + 255) / 256, 256, 0, s2>>>(adj_vals, rows, cols, e);
    cudaEventRecord(ev_join, s2);

    // main stream: gemm concurrent with CSR build
    gemm_tc_kernel<<<grid, 256, SMEM_TOTAL>>>(vecs, b0, att0, att1, attb0, attb1,
                                              off0, sc0, n, ntiles);
    cudaStreamWaitEvent(0, ev_join, 0);

    agg_kernel<<<(n + 7) / 8, 256>>>(b1, off1, sc1, out, n);
}

// round 11
// speedup vs baseline: 1.0713x; 1.0069x over previous
#include <cuda_runtime.h>
#include <cuda_bf16.h>
#include <cuda_fp16.h>
#include <cstdint>

#define MAXN 100000
#define MAXE 1600000

// ---------------- scratch (device globals; no allocation allowed) ----------
// B packed: [half(2)][split(2)][kchunk(8)][n(128)][16 bf16] = 131072 bytes
__device__ __align__(16) uint8_t g_Bpk[131072];
__device__ __align__(16) float  g_self[MAXN * 128];
__device__ __align__(16) __half g_vwh[MAXN * 128];     // fp16 vw for edge gather
__device__ __align__(16) float  g_a0[MAXN * 4];
__device__ __align__(16) float  g_a1[MAXN * 4];
__device__ int   g_cnt[MAXN];                          // FULL degree per dest row
__device__ int   g_start[MAXN];
__device__ int   g_cursor[MAXN];
__device__ int   g_ticket;                             // scan tile ticket
__device__ volatile unsigned int g_state[512];         // (status<<30)|sum
__device__ __align__(8) uint2 g_erec[MAXE];            // CSR records {col, val bits}

// ---------------- helpers ---------------------------------------------------
__device__ __forceinline__ uint32_t smem_u32(const void* p) {
    uint32_t a;
    asm("{ .reg .u64 t; cvta.to.shared.u64 t, %1; cvt.u32.u64 %0, t; }" : "=r"(a) : "l"(p));
    return a;
}
__device__ __forceinline__ void ldsm4(uint32_t addr, uint32_t& r0, uint32_t& r1,
                                      uint32_t& r2, uint32_t& r3) {
    asm volatile("ldmatrix.sync.aligned.m8n8.x4.shared.b16 {%0,%1,%2,%3}, [%4];"
                 : "=r"(r0), "=r"(r1), "=r"(r2), "=r"(r3) : "r"(addr));
}
__device__ __forceinline__ void mma16816(float* c, uint32_t a0, uint32_t a1, uint32_t a2,
                                         uint32_t a3, uint32_t b0, uint32_t b1) {
    asm volatile(
        "mma.sync.aligned.m16n8k16.row.col.f32.bf16.bf16.f32 "
        "{%0,%1,%2,%3},{%4,%5,%6,%7},{%8,%9},{%0,%1,%2,%3};"
        : "+f"(c[0]), "+f"(c[1]), "+f"(c[2]), "+f"(c[3])
        : "r"(a0), "r"(a1), "r"(a2), "r"(a3), "r"(b0), "r"(b1));
}

// SMEM: B resident [hf(2)][sp(2)][kc(8)][128][32B] = 131072
//       A [sp(2)][kc(8)][row(128)][32B]            = 65536
//       ex row exchange 128 rows x 2 halves float2 = 2048
#define SMEM_B 0
#define SMEM_A 131072
#define SMEM_EX (131072 + 65536)
#define SMEM_TOTAL (131072 + 65536 + 2048)

// ---------------- kernel 0: pack B (bf16 hi/lo) + zero cnt/scan state ------
__global__ __launch_bounds__(256) void pack_kernel(const float* __restrict__ W0,
                                                   const float* __restrict__ W1, int n) {
    int idx = blockIdx.x * 256 + threadIdx.x;
    if (idx < 32768) {
        int k = idx >> 8;          // 0..127
        int c = idx & 255;         // 0..255 global output col
        float v;
        if (c < 128) {
            v = W0[k * 128 + c];
        } else {
            int j = c - 128;
            int h = j >> 5;
            int k2 = j & 31;
            v = W1[(h * 128 + k) * 32 + k2];
        }
        __nv_bfloat16 hi = __float2bfloat16_rn(v);
        __nv_bfloat16 lo = __float2bfloat16_rn(v - __bfloat162float(hi));
        int hf = c >> 7;
        int nn = c & 127;
        int kc = k >> 4;
        int kk = k & 15;
        int base = ((hf * 2 + 0) * 8 + kc) * 4096 + nn * 32 + kk * 2;
        *reinterpret_cast<__nv_bfloat16*>(g_Bpk + base) = hi;
        *reinterpret_cast<__nv_bfloat16*>(g_Bpk + base + 32768) = lo;   // sp stride = 8*4096
    }
    if (idx < n) g_cnt[idx] = 0;
    if (idx < 512) g_state[idx] = 0;
    if (idx == 0) g_ticket = 0;
}

// ---------------- kernel 1: persistent mma.sync GEMM, fragment epilogues ----
__global__ __launch_bounds__(256, 1) void gemm_tc_kernel(
    const float* __restrict__ vecs, const float* __restrict__ b0,
    const float* __restrict__ att0, const float* __restrict__ att1,
    const float* __restrict__ attb0, const float* __restrict__ attb1,
    const float* __restrict__ off0, const float* __restrict__ sc0, int n, int ntiles) {
    extern __shared__ __align__(1024) char smem[];
    uint32_t sb = smem_u32(smem);
    float2* ex = reinterpret_cast<float2*>(smem + SMEM_EX);
    int tid = threadIdx.x;
    int wid = tid >> 5;
    int lane = tid & 31;

    int mrow0 = (wid & 3) * 32;
    int nbase = (wid >> 2) * 64;
    int rq = lane >> 2;          // row-in-8 selector
    int cq = 2 * (lane & 3);     // col pair selector

    int lt = lane >> 3;
    int l7 = lane & 7;
    int alane = ((lt & 1) * 8 + l7) * 32 + (lt >> 1) * 16;
    int blane = ((lt >> 1) * 8 + l7) * 32 + (lt & 1) * 16;

    // ---- load full B (131072 B) once, resident for kernel lifetime ----
    {
        const uint4* src = reinterpret_cast<const uint4*>(g_Bpk);
        uint4* dst = reinterpret_cast<uint4*>(smem + SMEM_B);
#pragma unroll
        for (int i = 0; i < 32; i++) dst[tid + i * 256] = __ldg(&src[tid + i * 256]);
    }
    __syncthreads();

    float acc[2][8][4];

    auto compute_pass = [&](int hf) {
#pragma unroll
        for (int mt = 0; mt < 2; mt++)
#pragma unroll
            for (int nf = 0; nf < 8; nf++)
#pragma unroll
                for (int q = 0; q < 4; q++) acc[mt][nf][q] = 0.f;
        uint32_t Bbase = sb + SMEM_B + hf * 65536;
        uint32_t Abase = sb + SMEM_A;
#pragma unroll
        for (int kc = 0; kc < 8; kc++) {
            uint32_t ah[2][4], al[2][4];
#pragma unroll
            for (int mt = 0; mt < 2; mt++) {
                uint32_t aaddr = Abase + kc * 4096 + (mrow0 + mt * 16) * 32 + alane;
                ldsm4(aaddr, ah[mt][0], ah[mt][1], ah[mt][2], ah[mt][3]);
                ldsm4(aaddr + 32768, al[mt][0], al[mt][1], al[mt][2], al[mt][3]);
            }
#pragma unroll
            for (int np = 0; np < 4; np++) {
                uint32_t bh[4], bl[4];
                uint32_t baddr = Bbase + kc * 4096 + (nbase + np * 16) * 32 + blane;
                ldsm4(baddr, bh[0], bh[1], bh[2], bh[3]);
                ldsm4(baddr + 32768, bl[0], bl[1], bl[2], bl[3]);
#pragma unroll
                for (int mt = 0; mt < 2; mt++)
#pragma unroll
                    for (int j = 0; j < 2; j++) {
                        float* c = acc[mt][np * 2 + j];
                        mma16816(c, ah[mt][0], ah[mt][1], ah[mt][2], ah[mt][3],
                                 bh[2 * j], bh[2 * j + 1]);
                        mma16816(c, ah[mt][0], ah[mt][1], ah[mt][2], ah[mt][3],
                                 bl[2 * j], bl[2 * j + 1]);
                        mma16816(c, al[mt][0], al[mt][1], al[mt][2], al[mt][3],
                                 bh[2 * j], bh[2 * j + 1]);
                    }
            }
        }
    };

    for (int tile = blockIdx.x; tile < ntiles; tile += gridDim.x) {
        int row0 = tile * 128;

        // ---- load A tile: fp32 -> bf16 hi/lo, [sp][kc][row][32B] ----
#pragma unroll
        for (int it = 0; it < 16; it++) {
            int t = it * 256 + tid;
            int r = t >> 5;
            int q = t & 31;
            float4 v = make_float4(0.f, 0.f, 0.f, 0.f);
            int gr = row0 + r;
            if (gr < n) v = __ldg(reinterpret_cast<const float4*>(vecs + (size_t)gr * 128 + q * 4));
            __nv_bfloat16 h0 = __float2bfloat16_rn(v.x), h1 = __float2bfloat16_rn(v.y);
            __nv_bfloat16 h2 = __float2bfloat16_rn(v.z), h3 = __float2bfloat16_rn(v.w);
            __nv_bfloat16 l0 = __float2bfloat16_rn(v.x - __bfloat162float(h0));
            __nv_bfloat16 l1 = __float2bfloat16_rn(v.y - __bfloat162float(h1));
            __nv_bfloat16 l2 = __float2bfloat16_rn(v.z - __bfloat162float(h2));
            __nv_bfloat16 l3 = __float2bfloat16_rn(v.w - __bfloat162float(h3));
            uint2 hv, lv;
            hv.x = ((uint32_t)__bfloat16_as_ushort(h1) << 16) | __bfloat16_as_ushort(h0);
            hv.y = ((uint32_t)__bfloat16_as_ushort(h3) << 16) | __bfloat16_as_ushort(h2);
            lv.x = ((uint32_t)__bfloat16_as_ushort(l1) << 16) | __bfloat16_as_ushort(l0);
            lv.y = ((uint32_t)__bfloat16_as_ushort(l3) << 16) | __bfloat16_as_ushort(l2);
            int kc = q >> 2;
            int kq = q & 3;
            int off = kc * 4096 + r * 32 + kq * 8;
            *reinterpret_cast<uint2*>(smem + SMEM_A + off) = hv;
            *reinterpret_cast<uint2*>(smem + SMEM_A + 32768 + off) = lv;
        }
        __syncthreads();

        // ===== pass 0: self path (cols 0..127) =====
        compute_pass(0);

        // ---- self epilogue from fragments ----
        {
            float sums[2][2] = {{0.f, 0.f}, {0.f, 0.f}};
            float sqs[2][2] = {{0.f, 0.f}, {0.f, 0.f}};
#pragma unroll
            for (int mt = 0; mt < 2; mt++)
#pragma unroll
                for (int nf = 0; nf < 8; nf++) {
                    int col = nbase + nf * 8 + cq;
                    float ba = __ldg(b0 + col), bb2 = __ldg(b0 + col + 1);
                    float t0 = fmaxf(acc[mt][nf][0] + ba, 0.f);
                    float t1 = fmaxf(acc[mt][nf][1] + bb2, 0.f);
                    float t2 = fmaxf(acc[mt][nf][2] + ba, 0.f);
                    float t3 = fmaxf(acc[mt][nf][3] + bb2, 0.f);
                    sums[mt][0] += t0 + t1; sqs[mt][0] += t0 * t0 + t1 * t1;
                    sums[mt][1] += t2 + t3; sqs[mt][1] += t2 * t2 + t3 * t3;
                }
#pragma unroll
            for (int mk = 1; mk <= 2; mk <<= 1)
#pragma unroll
                for (int mt = 0; mt < 2; mt++)
#pragma unroll
                    for (int hh = 0; hh < 2; hh++) {
                        sums[mt][hh] += __shfl_xor_sync(0xffffffffu, sums[mt][hh], mk);
                        sqs[mt][hh]  += __shfl_xor_sync(0xffffffffu, sqs[mt][hh], mk);
                    }
            int wh = wid >> 2;
            if ((lane & 3) == 0) {
#pragma unroll
                for (int mt = 0; mt < 2; mt++)
#pragma unroll
                    for (int hh = 0; hh < 2; hh++) {
                        int lr = mrow0 + mt * 16 + hh * 8 + rq;
                        ex[lr * 2 + wh] = make_float2(sums[mt][hh], sqs[mt][hh]);
                    }
            }
            __syncthreads();
            float meanv[2][2], rsv[2][2];
#pragma unroll
            for (int mt = 0; mt < 2; mt++)
#pragma unroll
                for (int hh = 0; hh < 2; hh++) {
                    int lr = mrow0 + mt * 16 + hh * 8 + rq;
                    float2 e0 = ex[lr * 2 + 0], e1 = ex[lr * 2 + 1];
                    float sum = e0.x + e1.x, sq = e0.y + e1.y;
                    float mean = sum * (1.f / 128.f);
                    float var = fmaxf(sq * (1.f / 128.f) - mean * mean, 0.f);
                    meanv[mt][hh] = mean;
                    rsv[mt][hh] = rsqrtf(var + 1e-9f);
                }
#pragma unroll
            for (int mt = 0; mt < 2; mt++) {
                int r0g = row0 + mrow0 + mt * 16 + rq;
#pragma unroll
                for (int nf = 0; nf < 8; nf++) {
                    int col = nbase + nf * 8 + cq;
                    float ba = __ldg(b0 + col), bb2 = __ldg(b0 + col + 1);
                    float sa = __ldg(sc0 + col), sb2 = __ldg(sc0 + col + 1);
                    float oa = __ldg(off0 + col), ob = __ldg(off0 + col + 1);
                    if (r0g < n) {
                        float t0 = fmaxf(acc[mt][nf][0] + ba, 0.f);
                        float t1 = fmaxf(acc[mt][nf][1] + bb2, 0.f);
                        *reinterpret_cast<float2*>(&g_self[(size_t)r0g * 128 + col]) =
                            make_float2(sa * (t0 - meanv[mt][0]) * rsv[mt][0] + oa,
                                        sb2 * (t1 - meanv[mt][0]) * rsv[mt][0] + ob);
                    }
                    if (r0g + 8 < n) {
                        float t2 = fmaxf(acc[mt][nf][2] + ba, 0.f);
                        float t3 = fmaxf(acc[mt][nf][3] + bb2, 0.f);
                        *reinterpret_cast<float2*>(&g_self[(size_t)(r0g + 8) * 128 + col]) =
                            make_float2(sa * (t2 - meanv[mt][1]) * rsv[mt][1] + oa,
                                        sb2 * (t3 - meanv[mt][1]) * rsv[mt][1] + ob);
                    }
                }
            }
        }

        // ===== pass 1: vw path (cols 128..255) =====
        compute_pass(1);

        // ---- vw epilogue: fp16 stores + attention dots from fragments ----
        {
            int h0 = nbase >> 5;
            float d0p[2][2][2], d1p[2][2][2];
#pragma unroll
            for (int mt = 0; mt < 2; mt++)
#pragma unroll
                for (int hh = 0; hh < 2; hh++)
#pragma unroll
                    for (int hs = 0; hs < 2; hs++) { d0p[mt][hh][hs] = 0.f; d1p[mt][hh][hs] = 0.f; }
#pragma unroll
            for (int mt = 0; mt < 2; mt++) {
                int r0g = row0 + mrow0 + mt * 16 + rq;
#pragma unroll
                for (int nf = 0; nf < 8; nf++) {
                    int col = nbase + nf * 8 + cq;
                    float a00 = __ldg(att0 + col), a01 = __ldg(att0 + col + 1);
                    float a10 = __ldg(att1 + col), a11 = __ldg(att1 + col + 1);
                    float v0 = acc[mt][nf][0], v1 = acc[mt][nf][1];
                    float v2 = acc[mt][nf][2], v3 = acc[mt][nf][3];
                    if (r0g < n) {
                        __half2 p = __floats2half2_rn(v0, v1);
                        *reinterpret_cast<__half2*>(&g_vwh[(size_t)r0g * 128 + col]) = p;
                    }
                    if (r0g + 8 < n) {
                        __half2 p = __floats2half2_rn(v2, v3);
                        *reinterpret_cast<__half2*>(&g_vwh[(size_t)(r0g + 8) * 128 + col]) = p;
                    }
                    int hs = nf >> 2;
                    d0p[mt][0][hs] += v0 * a00 + v1 * a01;
                    d0p[mt][1][hs] += v2 * a00 + v3 * a01;
                    d1p[mt][0][hs] += v0 * a10 + v1 * a11;
                    d1p[mt][1][hs] += v2 * a10 + v3 * a11;
                }
            }
#pragma unroll
            for (int mk = 1; mk <= 2; mk <<= 1)
#pragma unroll
                for (int mt = 0; mt < 2; mt++)
#pragma unroll
                    for (int hh = 0; hh < 2; hh++)
#pragma unroll
                        for (int hs = 0; hs < 2; hs++) {
                            d0p[mt][hh][hs] += __shfl_xor_sync(0xffffffffu, d0p[mt][hh][hs], mk);
                            d1p[mt][hh][hs] += __shfl_xor_sync(0xffffffffu, d1p[mt][hh][hs], mk);
                        }
            if ((lane & 3) == 0) {
#pragma unroll
                for (int mt = 0; mt < 2; mt++)
#pragma unroll
                    for (int hh = 0; hh < 2; hh++) {
                        int rg = row0 + mrow0 + mt * 16 + hh * 8 + rq;
                        if (rg < n) {
#pragma unroll
                            for (int hs = 0; hs < 2; hs++) {
                                g_a0[(size_t)rg * 4 + h0 + hs] =
                                    d0p[mt][hh][hs] + __ldg(attb0 + h0 + hs);
                                g_a1[(size_t)rg * 4 + h0 + hs] =
                                    d1p[mt][hh][hs] + __ldg(attb1 + h0 + hs);
                            }
                        }
                    }
            }
        }
        __syncthreads();   // protect A + ex before next tile overwrites
    }
}

// ---------------- kernel 2: full-degree histogram ----------------------------
__global__ __launch_bounds__(256) void hist_kernel(const int* __restrict__ rows, int e) {
    int i = blockIdx.x * 256 + threadIdx.x;
    if (i >= e) return;
    atomicAdd(&g_cnt[__ldg(rows + i)], 1);
}

// ---------------- kernel 3: single-pass decoupled-lookback scan -------------
__global__ __launch_bounds__(256) void scan_kernel(int n) {
    __shared__ int s_bid;
    __shared__ int s_wsum[8];
    __shared__ int s_prefix;
    int tid = threadIdx.x;
    int wid = tid >> 5;
    int lane = tid & 31;

    if (tid == 0) s_bid = atomicAdd(&g_ticket, 1);
    __syncthreads();
    int bid = s_bid;

    int i = bid * 256 + tid;
    int v = (i < n) ? g_cnt[i] : 0;

    int incl = v;
#pragma unroll
    for (int m = 1; m < 32; m <<= 1) {
        int x = __shfl_up_sync(0xffffffffu, incl, m);
        if (lane >= m) incl += x;
    }
    if (lane == 31) s_wsum[wid] = incl;
    __syncthreads();
    if (wid == 0 && lane < 8) {
        int w = s_wsum[lane];
#pragma unroll
        for (int m = 1; m < 8; m <<= 1) {
            int x = __shfl_up_sync(0xffu, w, m);
            if (lane >= m) w += x;
        }
        s_wsum[lane] = w;
    }
    __syncthreads();
    int blocksum = s_wsum[7];
    if (wid > 0) incl += s_wsum[wid - 1];

    if (tid == 0) {
        unsigned int tag = (bid == 0) ? ((2u << 30) | (unsigned int)blocksum)
                                      : ((1u << 30) | (unsigned int)blocksum);
        g_state[bid] = tag;
        __threadfence();
    }

    if (wid == 0) {
        int prefix = 0;
        if (bid > 0) {
            int look = bid - 1;
            while (true) {
                int idx2 = look - lane;
                unsigned int st;
                if (idx2 < 0) {
                    st = (2u << 30);
                } else {
                    do { st = g_state[idx2]; } while ((st >> 30) == 0u);
                }
                unsigned int status = st >> 30;
                int val = (int)(st & 0x3FFFFFFFu);
                unsigned int ball = __ballot_sync(0xffffffffu, status >= 2u);
                if (ball) {
                    int first = __ffs(ball) - 1;
                    int contrib = (lane <= first) ? val : 0;
#pragma unroll
                    for (int m = 16; m > 0; m >>= 1)
                        contrib += __shfl_xor_sync(0xffffffffu, contrib, m);
                    prefix += contrib;
                    break;
                } else {
                    int contrib = val;
#pragma unroll
                    for (int m = 16; m > 0; m >>= 1)
                        contrib += __shfl_xor_sync(0xffffffffu, contrib, m);
                    prefix += contrib;
                    look -= 32;
                }
            }
            if (lane == 0) {
                g_state[bid] = (2u << 30) | (unsigned int)(prefix + blocksum);
                __threadfence();
            }
        }
        if (lane == 0) s_prefix = prefix;
    }
    __syncthreads();

    if (i < n) {
        int start = s_prefix + incl - v;
        g_start[i] = start;
        g_cursor[i] = start;
    }
}

// ---------------- kernel 4: CSR scatter (no attention dependency) -----------
__global__ __launch_bounds__(256) void scatter_kernel(const float* __restrict__ vals,
                                                      const int* __restrict__ rows,
                                                      const int* __restrict__ cols, int e) {
    int i = blockIdx.x * 256 + threadIdx.x;
    if (i >= e) return;
    int r = __ldg(rows + i);
    int c = __ldg(cols + i);
    float val = __ldg(vals + i);
    int pos = atomicAdd(&g_cursor[r], 1);
    g_erec[pos] = make_uint2((unsigned int)c, __float_as_uint(val));
}

// ---------------- kernel 5: per-row aggregation, batched pipeline -----------
__global__ __launch_bounds__(256) void agg_kernel(const float* __restrict__ b1,
                                                  const float* __restrict__ off1,
                                                  const float* __restrict__ sc1,
                                                  float* __restrict__ out, int n) {
    int r = (blockIdx.x << 3) + (threadIdx.x >> 5);
    if (r >= n) return;
    int lane = threadIdx.x & 31;
    int j = lane << 2;
    int h = lane >> 3;

    int start = g_start[r];
    int deg = g_cnt[r];
    float a0h = __ldg(&g_a0[(size_t)r * 4 + h]);

    float4 acc = make_float4(0.f, 0.f, 0.f, 0.f);

    int i = 0;
    for (; i + 8 <= deg; i += 8) {
        // phase 1: 8 independent record loads
        uint2 rec[8];
#pragma unroll
        for (int u = 0; u < 8; u++) rec[u] = __ldg(&g_erec[start + i + u]);
        // phase 2: 8 independent a1 gathers
        float a1v[8];
#pragma unroll
        for (int u = 0; u < 8; u++)
            a1v[u] = __ldg(&g_a1[(size_t)rec[u].x * 4 + h]);
        // phase 3: weights
        float w[8];
#pragma unroll
        for (int u = 0; u < 8; u++)
            w[u] = __uint_as_float(rec[u].y) * fmaxf(a0h + a1v[u], 0.f);
        // phase 4: independent conditional feature gathers + accumulate
#pragma unroll
        for (int u = 0; u < 8; u++) {
            if (w[u] > 0.f) {
                uint2 pk = __ldg(reinterpret_cast<const uint2*>(
                    &g_vwh[(size_t)rec[u].x * 128 + j]));
                float2 v0 = __half22float2(*reinterpret_cast<__half2*>(&pk.x));
                float2 v1 = __half22float2(*reinterpret_cast<__half2*>(&pk.y));
                acc.x += w[u] * v0.x;
                acc.y += w[u] * v0.y;
                acc.z += w[u] * v1.x;
                acc.w += w[u] * v1.y;
            }
        }
    }
    for (; i < deg; i++) {
        uint2 rec = __ldg(&g_erec[start + i]);
        float a1h = __ldg(&g_a1[(size_t)rec.x * 4 + h]);
        float w = __uint_as_float(rec.y) * fmaxf(a0h + a1h, 0.f);
        if (w > 0.f) {
            uint2 pk = __ldg(reinterpret_cast<const uint2*>(&g_vwh[(size_t)rec.x * 128 + j]));
            float2 v0 = __half22float2(*reinterpret_cast<__half2*>(&pk.x));
            float2 v1 = __half22float2(*reinterpret_cast<__half2*>(&pk.y));
            acc.x += w * v0.x;
            acc.y += w * v0.y;
            acc.z += w * v1.x;
            acc.w += w * v1.y;
        }
    }

    float t0 = fmaxf(acc.x, 0.f) + b1[j + 0];
    float t1 = fmaxf(acc.y, 0.f) + b1[j + 1];
    float t2 = fmaxf(acc.z, 0.f) + b1[j + 2];
    float t3 = fmaxf(acc.w, 0.f) + b1[j + 3];
    float sum = t0 + t1 + t2 + t3;
    float sq = t0 * t0 + t1 * t1 + t2 * t2 + t3 * t3;
#pragma unroll
    for (int m = 16; m > 0; m >>= 1) {
        sum += __shfl_xor_sync(0xffffffffu, sum, m);
        sq  += __shfl_xor_sync(0xffffffffu, sq, m);
    }
    float mean = sum * (1.f / 128.f);
    float var = fmaxf(sq * (1.f / 128.f) - mean * mean, 0.f);
    float rs = rsqrtf(var + 1e-9f);
    float4 s = *reinterpret_cast<const float4*>(&g_self[(size_t)r * 128 + j]);
    float4 o;
    o.x = sc1[j + 0] * (t0 - mean) * rs + off1[j + 0] + s.x;
    o.y = sc1[j + 1] * (t1 - mean) * rs + off1[j + 1] + s.y;
    o.z = sc1[j + 2] * (t2 - mean) * rs + off1[j + 2] + s.z;
    o.w = sc1[j + 3] * (t3 - mean) * rs + off1[j + 3] + s.w;
    *reinterpret_cast<float4*>(&out[(size_t)r * 128 + j]) = o;
}

// ---------------- launch ----------------------------------------------------
extern "C" void kernel_launch(void* const* d_in, const int* in_sizes, int n_in,
                              void* d_out, int out_size) {
    const float* vecs     = (const float*)d_in[0];
    const float* adj_vals = (const float*)d_in[1];
    const float* W0       = (const float*)d_in[2];
    const float* b0       = (const float*)d_in[3];
    const float* W1       = (const float*)d_in[4];
    const float* b1       = (const float*)d_in[5];
    const float* att0     = (const float*)d_in[6];
    const float* att1     = (const float*)d_in[7];
    const float* attb0    = (const float*)d_in[8];
    const float* attb1    = (const float*)d_in[9];
    const float* off0     = (const float*)d_in[10];
    const float* sc0      = (const float*)d_in[11];
    const float* off1     = (const float*)d_in[12];
    const float* sc1      = (const float*)d_in[13];
    const int*   rows     = (const int*)d_in[14];
    const int*   cols     = (const int*)d_in[15];

    int n = in_sizes[0] / 128;
    int e = in_sizes[1];
    float* out = (float*)d_out;

    int nb = (n + 255) / 256;
    int nbp = nb < 128 ? 128 : nb;
    int ntiles = (n + 127) / 128;
    int grid = ntiles < 152 ? ntiles : 152;

    static cudaStream_t s2 = nullptr;
    static cudaEvent_t ev_fork = nullptr, ev_join = nullptr;
    static int smem_set = 0;
    if (!smem_set) {
        cudaFuncSetAttribute(gemm_tc_kernel, cudaFuncAttributeMaxDynamicSharedMemorySize,
                             SMEM_TOTAL);
        cudaStreamCreateWithFlags(&s2, cudaStreamNonBlocking);
        cudaEventCreateWithFlags(&ev_fork, cudaEventDisableTiming);
        cudaEventCreateWithFlags(&ev_join, cudaEventDisableTiming);
        smem_set = 1;
    }

    pack_kernel<<<nbp, 256>>>(W0, W1, n);
    cudaEventRecord(ev_fork, 0);
    cudaStreamWaitEvent(s2, ev_fork, 0);

    // side stream: entire CSR build, independent of the GEMM
    hist_kernel<<<(e + 255) / 256, 256, 0, s2>>>(rows, e);
    scan_kernel<<<nb, 256, 0, s2>>>(n);
    scatter_kernel<<<(e + 255) / 256, 256, 0, s2>>>(adj_vals, rows, cols, e);
    cudaEventRecord(ev_join, s2);

    // main stream: gemm concurrent with CSR build
    gemm_tc_kernel<<<grid, 256, SMEM_TOTAL>>>(vecs, b0, att0, att1, attb0, attb1,
                                              off0, sc0, n, ntiles);
    cudaStreamWaitEvent(0, ev_join, 0);

    agg_kernel<<<(n + 7) / 8, 256>>>(b1, off1, sc1, out, n);
}

// round 12
// speedup vs baseline: 1.1466x; 1.0702x over previous
#include <cuda_runtime.h>
#include <cuda_bf16.h>
#include <cuda_fp16.h>
#include <cstdint>

#define MAXN 100000
#define MAXE 1600000

// ---------------- scratch (device globals; no allocation allowed) ----------
// B packed: [half(2)][split(2)][kchunk(8)][n(128)][16 bf16] = 131072 bytes
__device__ __align__(16) uint8_t g_Bpk[131072];
__device__ __align__(16) float  g_self[MAXN * 128];
__device__ __align__(16) __half g_vwh[MAXN * 128];     // fp16 vw for edge gather
__device__ __align__(16) float  g_a0[MAXN * 4];
__device__ __align__(16) float  g_a1[MAXN * 4];
__device__ int   g_cnt[MAXN];                          // FULL degree per dest row
__device__ int   g_start[MAXN];
__device__ int   g_cursor[MAXN];
__device__ int   g_ticket;                             // scan tile ticket
__device__ volatile unsigned int g_state[512];         // (status<<30)|sum
__device__ __align__(8) uint2 g_erec[MAXE];            // CSR records {col, val bits}

// ---------------- helpers ---------------------------------------------------
__device__ __forceinline__ uint32_t smem_u32(const void* p) {
    uint32_t a;
    asm("{ .reg .u64 t; cvta.to.shared.u64 t, %1; cvt.u32.u64 %0, t; }" : "=r"(a) : "l"(p));
    return a;
}
__device__ __forceinline__ void ldsm4(uint32_t addr, uint32_t& r0, uint32_t& r1,
                                      uint32_t& r2, uint32_t& r3) {
    asm volatile("ldmatrix.sync.aligned.m8n8.x4.shared.b16 {%0,%1,%2,%3}, [%4];"
                 : "=r"(r0), "=r"(r1), "=r"(r2), "=r"(r3) : "r"(addr));
}
__device__ __forceinline__ void mma16816(float* c, uint32_t a0, uint32_t a1, uint32_t a2,
                                         uint32_t a3, uint32_t b0, uint32_t b1) {
    asm volatile(
        "mma.sync.aligned.m16n8k16.row.col.f32.bf16.bf16.f32 "
        "{%0,%1,%2,%3},{%4,%5,%6,%7},{%8,%9},{%0,%1,%2,%3};"
        : "+f"(c[0]), "+f"(c[1]), "+f"(c[2]), "+f"(c[3])
        : "r"(a0), "r"(a1), "r"(a2), "r"(a3), "r"(b0), "r"(b1));
}

// SMEM: B resident [hf(2)][sp(2)][kc(8)][128][32B] = 131072
//       A [sp(2)][kc(8)][row(128)][32B]            = 65536
//       ex row exchange 128 rows x 2 halves float2 = 2048
#define SMEM_B 0
#define SMEM_A 131072
#define SMEM_EX (131072 + 65536)
#define SMEM_TOTAL (131072 + 65536 + 2048)

// ---------------- kernel 0: pack B (bf16 hi/lo) + zero cnt/scan state ------
__global__ __launch_bounds__(256) void pack_kernel(const float* __restrict__ W0,
                                                   const float* __restrict__ W1, int n) {
    int idx = blockIdx.x * 256 + threadIdx.x;
    if (idx < 32768) {
        int k = idx >> 8;          // 0..127
        int c = idx & 255;         // 0..255 global output col
        float v;
        if (c < 128) {
            v = W0[k * 128 + c];
        } else {
            int j = c - 128;
            int h = j >> 5;
            int k2 = j & 31;
            v = W1[(h * 128 + k) * 32 + k2];
        }
        __nv_bfloat16 hi = __float2bfloat16_rn(v);
        __nv_bfloat16 lo = __float2bfloat16_rn(v - __bfloat162float(hi));
        int hf = c >> 7;
        int nn = c & 127;
        int kc = k >> 4;
        int kk = k & 15;
        int base = ((hf * 2 + 0) * 8 + kc) * 4096 + nn * 32 + kk * 2;
        *reinterpret_cast<__nv_bfloat16*>(g_Bpk + base) = hi;
        *reinterpret_cast<__nv_bfloat16*>(g_Bpk + base + 32768) = lo;   // sp stride = 8*4096
    }
    if (idx < n) g_cnt[idx] = 0;
    if (idx < 512) g_state[idx] = 0;
    if (idx == 0) g_ticket = 0;
}

// ---------------- kernel 1: persistent mma.sync GEMM, fragment epilogues ----
__global__ __launch_bounds__(256, 1) void gemm_tc_kernel(
    const float* __restrict__ vecs, const float* __restrict__ b0,
    const float* __restrict__ att0, const float* __restrict__ att1,
    const float* __restrict__ attb0, const float* __restrict__ attb1,
    const float* __restrict__ off0, const float* __restrict__ sc0, int n, int ntiles) {
    extern __shared__ __align__(1024) char smem[];
    uint32_t sb = smem_u32(smem);
    float2* ex = reinterpret_cast<float2*>(smem + SMEM_EX);
    int tid = threadIdx.x;
    int wid = tid >> 5;
    int lane = tid & 31;

    int mrow0 = (wid & 3) * 32;
    int nbase = (wid >> 2) * 64;
    int rq = lane >> 2;          // row-in-8 selector
    int cq = 2 * (lane & 3);     // col pair selector

    int lt = lane >> 3;
    int l7 = lane & 7;
    int alane = ((lt & 1) * 8 + l7) * 32 + (lt >> 1) * 16;
    int blane = ((lt >> 1) * 8 + l7) * 32 + (lt & 1) * 16;

    // ---- load full B (131072 B) once, resident for kernel lifetime ----
    {
        const uint4* src = reinterpret_cast<const uint4*>(g_Bpk);
        uint4* dst = reinterpret_cast<uint4*>(smem + SMEM_B);
#pragma unroll
        for (int i = 0; i < 32; i++) dst[tid + i * 256] = __ldg(&src[tid + i * 256]);
    }
    __syncthreads();

    float acc[2][8][4];

    auto compute_pass = [&](int hf) {
#pragma unroll
        for (int mt = 0; mt < 2; mt++)
#pragma unroll
            for (int nf = 0; nf < 8; nf++)
#pragma unroll
                for (int q = 0; q < 4; q++) acc[mt][nf][q] = 0.f;
        uint32_t Bbase = sb + SMEM_B + hf * 65536;
        uint32_t Abase = sb + SMEM_A;
#pragma unroll
        for (int kc = 0; kc < 8; kc++) {
            uint32_t ah[2][4], al[2][4];
#pragma unroll
            for (int mt = 0; mt < 2; mt++) {
                uint32_t aaddr = Abase + kc * 4096 + (mrow0 + mt * 16) * 32 + alane;
                ldsm4(aaddr, ah[mt][0], ah[mt][1], ah[mt][2], ah[mt][3]);
                ldsm4(aaddr + 32768, al[mt][0], al[mt][1], al[mt][2], al[mt][3]);
            }
#pragma unroll
            for (int np = 0; np < 4; np++) {
                uint32_t bh[4], bl[4];
                uint32_t baddr = Bbase + kc * 4096 + (nbase + np * 16) * 32 + blane;
                ldsm4(baddr, bh[0], bh[1], bh[2], bh[3]);
                ldsm4(baddr + 32768, bl[0], bl[1], bl[2], bl[3]);
#pragma unroll
                for (int mt = 0; mt < 2; mt++)
#pragma unroll
                    for (int j = 0; j < 2; j++) {
                        float* c = acc[mt][np * 2 + j];
                        mma16816(c, ah[mt][0], ah[mt][1], ah[mt][2], ah[mt][3],
                                 bh[2 * j], bh[2 * j + 1]);
                        mma16816(c, ah[mt][0], ah[mt][1], ah[mt][2], ah[mt][3],
                                 bl[2 * j], bl[2 * j + 1]);
                        mma16816(c, al[mt][0], al[mt][1], al[mt][2], al[mt][3],
                                 bh[2 * j], bh[2 * j + 1]);
                    }
            }
        }
    };

    for (int tile = blockIdx.x; tile < ntiles; tile += gridDim.x) {
        int row0 = tile * 128;

        // ---- load A tile: fp32 -> bf16 hi/lo, [sp][kc][row][32B] ----
#pragma unroll
        for (int it = 0; it < 16; it++) {
            int t = it * 256 + tid;
            int r = t >> 5;
            int q = t & 31;
            float4 v = make_float4(0.f, 0.f, 0.f, 0.f);
            int gr = row0 + r;
            if (gr < n) v = __ldg(reinterpret_cast<const float4*>(vecs + (size_t)gr * 128 + q * 4));
            __nv_bfloat16 h0 = __float2bfloat16_rn(v.x), h1 = __float2bfloat16_rn(v.y);
            __nv_bfloat16 h2 = __float2bfloat16_rn(v.z), h3 = __float2bfloat16_rn(v.w);
            __nv_bfloat16 l0 = __float2bfloat16_rn(v.x - __bfloat162float(h0));
            __nv_bfloat16 l1 = __float2bfloat16_rn(v.y - __bfloat162float(h1));
            __nv_bfloat16 l2 = __float2bfloat16_rn(v.z - __bfloat162float(h2));
            __nv_bfloat16 l3 = __float2bfloat16_rn(v.w - __bfloat162float(h3));
            uint2 hv, lv;
            hv.x = ((uint32_t)__bfloat16_as_ushort(h1) << 16) | __bfloat16_as_ushort(h0);
            hv.y = ((uint32_t)__bfloat16_as_ushort(h3) << 16) | __bfloat16_as_ushort(h2);
            lv.x = ((uint32_t)__bfloat16_as_ushort(l1) << 16) | __bfloat16_as_ushort(l0);
            lv.y = ((uint32_t)__bfloat16_as_ushort(l3) << 16) | __bfloat16_as_ushort(l2);
            int kc = q >> 2;
            int kq = q & 3;
            int off = kc * 4096 + r * 32 + kq * 8;
            *reinterpret_cast<uint2*>(smem + SMEM_A + off) = hv;
            *reinterpret_cast<uint2*>(smem + SMEM_A + 32768 + off) = lv;
        }
        __syncthreads();

        // ===== pass 0: self path (cols 0..127) =====
        compute_pass(0);

        // ---- self epilogue from fragments ----
        {
            float sums[2][2] = {{0.f, 0.f}, {0.f, 0.f}};
            float sqs[2][2] = {{0.f, 0.f}, {0.f, 0.f}};
#pragma unroll
            for (int mt = 0; mt < 2; mt++)
#pragma unroll
                for (int nf = 0; nf < 8; nf++) {
                    int col = nbase + nf * 8 + cq;
                    float ba = __ldg(b0 + col), bb2 = __ldg(b0 + col + 1);
                    float t0 = fmaxf(acc[mt][nf][0] + ba, 0.f);
                    float t1 = fmaxf(acc[mt][nf][1] + bb2, 0.f);
                    float t2 = fmaxf(acc[mt][nf][2] + ba, 0.f);
                    float t3 = fmaxf(acc[mt][nf][3] + bb2, 0.f);
                    sums[mt][0] += t0 + t1; sqs[mt][0] += t0 * t0 + t1 * t1;
                    sums[mt][1] += t2 + t3; sqs[mt][1] += t2 * t2 + t3 * t3;
                }
#pragma unroll
            for (int mk = 1; mk <= 2; mk <<= 1)
#pragma unroll
                for (int mt = 0; mt < 2; mt++)
#pragma unroll
                    for (int hh = 0; hh < 2; hh++) {
                        sums[mt][hh] += __shfl_xor_sync(0xffffffffu, sums[mt][hh], mk);
                        sqs[mt][hh]  += __shfl_xor_sync(0xffffffffu, sqs[mt][hh], mk);
                    }
            int wh = wid >> 2;
            if ((lane & 3) == 0) {
#pragma unroll
                for (int mt = 0; mt < 2; mt++)
#pragma unroll
                    for (int hh = 0; hh < 2; hh++) {
                        int lr = mrow0 + mt * 16 + hh * 8 + rq;
                        ex[lr * 2 + wh] = make_float2(sums[mt][hh], sqs[mt][hh]);
                    }
            }
            __syncthreads();
            float meanv[2][2], rsv[2][2];
#pragma unroll
            for (int mt = 0; mt < 2; mt++)
#pragma unroll
                for (int hh = 0; hh < 2; hh++) {
                    int lr = mrow0 + mt * 16 + hh * 8 + rq;
                    float2 e0 = ex[lr * 2 + 0], e1 = ex[lr * 2 + 1];
                    float sum = e0.x + e1.x, sq = e0.y + e1.y;
                    float mean = sum * (1.f / 128.f);
                    float var = fmaxf(sq * (1.f / 128.f) - mean * mean, 0.f);
                    meanv[mt][hh] = mean;
                    rsv[mt][hh] = rsqrtf(var + 1e-9f);
                }
#pragma unroll
            for (int mt = 0; mt < 2; mt++) {
                int r0g = row0 + mrow0 + mt * 16 + rq;
#pragma unroll
                for (int nf = 0; nf < 8; nf++) {
                    int col = nbase + nf * 8 + cq;
                    float ba = __ldg(b0 + col), bb2 = __ldg(b0 + col + 1);
                    float sa = __ldg(sc0 + col), sb2 = __ldg(sc0 + col + 1);
                    float oa = __ldg(off0 + col), ob = __ldg(off0 + col + 1);
                    if (r0g < n) {
                        float t0 = fmaxf(acc[mt][nf][0] + ba, 0.f);
                        float t1 = fmaxf(acc[mt][nf][1] + bb2, 0.f);
                        *reinterpret_cast<float2*>(&g_self[(size_t)r0g * 128 + col]) =
                            make_float2(sa * (t0 - meanv[mt][0]) * rsv[mt][0] + oa,
                                        sb2 * (t1 - meanv[mt][0]) * rsv[mt][0] + ob);
                    }
                    if (r0g + 8 < n) {
                        float t2 = fmaxf(acc[mt][nf][2] + ba, 0.f);
                        float t3 = fmaxf(acc[mt][nf][3] + bb2, 0.f);
                        *reinterpret_cast<float2*>(&g_self[(size_t)(r0g + 8) * 128 + col]) =
                            make_float2(sa * (t2 - meanv[mt][1]) * rsv[mt][1] + oa,
                                        sb2 * (t3 - meanv[mt][1]) * rsv[mt][1] + ob);
                    }
                }
            }
        }

        // ===== pass 1: vw path (cols 128..255) =====
        compute_pass(1);

        // ---- vw epilogue: fp16 stores + attention dots from fragments ----
        {
            int h0 = nbase >> 5;
            float d0p[2][2][2], d1p[2][2][2];
#pragma unroll
            for (int mt = 0; mt < 2; mt++)
#pragma unroll
                for (int hh = 0; hh < 2; hh++)
#pragma unroll
                    for (int hs = 0; hs < 2; hs++) { d0p[mt][hh][hs] = 0.f; d1p[mt][hh][hs] = 0.f; }
#pragma unroll
            for (int mt = 0; mt < 2; mt++) {
                int r0g = row0 + mrow0 + mt * 16 + rq;
#pragma unroll
                for (int nf = 0; nf < 8; nf++) {
                    int col = nbase + nf * 8 + cq;
                    float a00 = __ldg(att0 + col), a01 = __ldg(att0 + col + 1);
                    float a10 = __ldg(att1 + col), a11 = __ldg(att1 + col + 1);
                    float v0 = acc[mt][nf][0], v1 = acc[mt][nf][1];
                    float v2 = acc[mt][nf][2], v3 = acc[mt][nf][3];
                    if (r0g < n) {
                        __half2 p = __floats2half2_rn(v0, v1);
                        *reinterpret_cast<__half2*>(&g_vwh[(size_t)r0g * 128 + col]) = p;
                    }
                    if (r0g + 8 < n) {
                        __half2 p = __floats2half2_rn(v2, v3);
                        *reinterpret_cast<__half2*>(&g_vwh[(size_t)(r0g + 8) * 128 + col]) = p;
                    }
                    int hs = nf >> 2;
                    d0p[mt][0][hs] += v0 * a00 + v1 * a01;
                    d0p[mt][1][hs] += v2 * a00 + v3 * a01;
                    d1p[mt][0][hs] += v0 * a10 + v1 * a11;
                    d1p[mt][1][hs] += v2 * a10 + v3 * a11;
                }
            }
#pragma unroll
            for (int mk = 1; mk <= 2; mk <<= 1)
#pragma unroll
                for (int mt = 0; mt < 2; mt++)
#pragma unroll
                    for (int hh = 0; hh < 2; hh++)
#pragma unroll
                        for (int hs = 0; hs < 2; hs++) {
                            d0p[mt][hh][hs] += __shfl_xor_sync(0xffffffffu, d0p[mt][hh][hs], mk);
                            d1p[mt][hh][hs] += __shfl_xor_sync(0xffffffffu, d1p[mt][hh][hs], mk);
                        }
            if ((lane & 3) == 0) {
#pragma unroll
                for (int mt = 0; mt < 2; mt++)
#pragma unroll
                    for (int hh = 0; hh < 2; hh++) {
                        int rg = row0 + mrow0 + mt * 16 + hh * 8 + rq;
                        if (rg < n) {
#pragma unroll
                            for (int hs = 0; hs < 2; hs++) {
                                g_a0[(size_t)rg * 4 + h0 + hs] =
                                    d0p[mt][hh][hs] + __ldg(attb0 + h0 + hs);
                                g_a1[(size_t)rg * 4 + h0 + hs] =
                                    d1p[mt][hh][hs] + __ldg(attb1 + h0 + hs);
                            }
                        }
                    }
            }
        }
        __syncthreads();   // protect A + ex before next tile overwrites
    }
}

// ---------------- kernel 2: full-degree histogram ----------------------------
__global__ __launch_bounds__(256) void hist_kernel(const int* __restrict__ rows, int e) {
    int i = blockIdx.x * 256 + threadIdx.x;
    if (i >= e) return;
    atomicAdd(&g_cnt[__ldg(rows + i)], 1);
}

// ---------------- kernel 3: single-pass decoupled-lookback scan -------------
__global__ __launch_bounds__(256) void scan_kernel(int n) {
    __shared__ int s_bid;
    __shared__ int s_wsum[8];
    __shared__ int s_prefix;
    int tid = threadIdx.x;
    int wid = tid >> 5;
    int lane = tid & 31;

    if (tid == 0) s_bid = atomicAdd(&g_ticket, 1);
    __syncthreads();
    int bid = s_bid;

    int i = bid * 256 + tid;
    int v = (i < n) ? g_cnt[i] : 0;

    int incl = v;
#pragma unroll
    for (int m = 1; m < 32; m <<= 1) {
        int x = __shfl_up_sync(0xffffffffu, incl, m);
        if (lane >= m) incl += x;
    }
    if (lane == 31) s_wsum[wid] = incl;
    __syncthreads();
    if (wid == 0 && lane < 8) {
        int w = s_wsum[lane];
#pragma unroll
        for (int m = 1; m < 8; m <<= 1) {
            int x = __shfl_up_sync(0xffu, w, m);
            if (lane >= m) w += x;
        }
        s_wsum[lane] = w;
    }
    __syncthreads();
    int blocksum = s_wsum[7];
    if (wid > 0) incl += s_wsum[wid - 1];

    if (tid == 0) {
        unsigned int tag = (bid == 0) ? ((2u << 30) | (unsigned int)blocksum)
                                      : ((1u << 30) | (unsigned int)blocksum);
        g_state[bid] = tag;
        __threadfence();
    }

    if (wid == 0) {
        int prefix = 0;
        if (bid > 0) {
            int look = bid - 1;
            while (true) {
                int idx2 = look - lane;
                unsigned int st;
                if (idx2 < 0) {
                    st = (2u << 30);
                } else {
                    do { st = g_state[idx2]; } while ((st >> 30) == 0u);
                }
                unsigned int status = st >> 30;
                int val = (int)(st & 0x3FFFFFFFu);
                unsigned int ball = __ballot_sync(0xffffffffu, status >= 2u);
                if (ball) {
                    int first = __ffs(ball) - 1;
                    int contrib = (lane <= first) ? val : 0;
#pragma unroll
                    for (int m = 16; m > 0; m >>= 1)
                        contrib += __shfl_xor_sync(0xffffffffu, contrib, m);
                    prefix += contrib;
                    break;
                } else {
                    int contrib = val;
#pragma unroll
                    for (int m = 16; m > 0; m >>= 1)
                        contrib += __shfl_xor_sync(0xffffffffu, contrib, m);
                    prefix += contrib;
                    look -= 32;
                }
            }
            if (lane == 0) {
                g_state[bid] = (2u << 30) | (unsigned int)(prefix + blocksum);
                __threadfence();
            }
        }
        if (lane == 0) s_prefix = prefix;
    }
    __syncthreads();

    if (i < n) {
        int start = s_prefix + incl - v;
        g_start[i] = start;
        g_cursor[i] = start;
    }
}

// ---------------- kernel 4: CSR scatter (no attention dependency) -----------
__global__ __launch_bounds__(256) void scatter_kernel(const float* __restrict__ vals,
                                                      const int* __restrict__ rows,
                                                      const int* __restrict__ cols, int e) {
    int i = blockIdx.x * 256 + threadIdx.x;
    if (i >= e) return;
    int r = __ldg(rows + i);
    int c = __ldg(cols + i);
    float val = __ldg(vals + i);
    int pos = atomicAdd(&g_cursor[r], 1);
    g_erec[pos] = make_uint2((unsigned int)c, __float_as_uint(val));
}

// ---------------- kernel 5: per-row aggregation, fully batched gathers ------
__global__ __launch_bounds__(256) void agg_kernel(const float* __restrict__ b1,
                                                  const float* __restrict__ off1,
                                                  const float* __restrict__ sc1,
                                                  float* __restrict__ out, int n) {
    int r = (blockIdx.x << 3) + (threadIdx.x >> 5);
    if (r >= n) return;
    int lane = threadIdx.x & 31;
    int j = lane << 2;
    int h = lane >> 3;

    int start = g_start[r];
    int deg = g_cnt[r];
    float a0h = __ldg(&g_a0[(size_t)r * 4 + h]);

    float4 acc = make_float4(0.f, 0.f, 0.f, 0.f);

    int i = 0;
    for (; i + 8 <= deg; i += 8) {
        // phase 1: 8 independent record loads (broadcast)
        uint2 rec[8];
#pragma unroll
        for (int u = 0; u < 8; u++) rec[u] = __ldg(&g_erec[start + i + u]);
        // phase 2: 8 independent a1 gathers
        float a1v[8];
#pragma unroll
        for (int u = 0; u < 8; u++)
            a1v[u] = __ldg(&g_a1[(size_t)rec[u].x * 4 + h]);
        // phase 3: 8 independent UNCONDITIONAL feature gathers (real MLP)
        uint2 pk[8];
#pragma unroll
        for (int u = 0; u < 8; u++)
            pk[u] = __ldg(reinterpret_cast<const uint2*>(&g_vwh[(size_t)rec[u].x * 128 + j]));
        // phase 4: branchless weights + FMAs (w == 0 for failing edges)
#pragma unroll
        for (int u = 0; u < 8; u++) {
            float w = __uint_as_float(rec[u].y) * fmaxf(a0h + a1v[u], 0.f);
            float2 v0 = __half22float2(*reinterpret_cast<__half2*>(&pk[u].x));
            float2 v1 = __half22float2(*reinterpret_cast<__half2*>(&pk[u].y));
            acc.x += w * v0.x;
            acc.y += w * v0.y;
            acc.z += w * v1.x;
            acc.w += w * v1.y;
        }
    }
    for (; i < deg; i++) {
        uint2 rec = __ldg(&g_erec[start + i]);
        float a1h = __ldg(&g_a1[(size_t)rec.x * 4 + h]);
        uint2 pk = __ldg(reinterpret_cast<const uint2*>(&g_vwh[(size_t)rec.x * 128 + j]));
        float w = __uint_as_float(rec.y) * fmaxf(a0h + a1h, 0.f);
        float2 v0 = __half22float2(*reinterpret_cast<__half2*>(&pk.x));
        float2 v1 = __half22float2(*reinterpret_cast<__half2*>(&pk.y));
        acc.x += w * v0.x;
        acc.y += w * v0.y;
        acc.z += w * v1.x;
        acc.w += w * v1.y;
    }

    float t0 = fmaxf(acc.x, 0.f) + b1[j + 0];
    float t1 = fmaxf(acc.y, 0.f) + b1[j + 1];
    float t2 = fmaxf(acc.z, 0.f) + b1[j + 2];
    float t3 = fmaxf(acc.w, 0.f) + b1[j + 3];
    float sum = t0 + t1 + t2 + t3;
    float sq = t0 * t0 + t1 * t1 + t2 * t2 + t3 * t3;
#pragma unroll
    for (int m = 16; m > 0; m >>= 1) {
        sum += __shfl_xor_sync(0xffffffffu, sum, m);
        sq  += __shfl_xor_sync(0xffffffffu, sq, m);
    }
    float mean = sum * (1.f / 128.f);
    float var = fmaxf(sq * (1.f / 128.f) - mean * mean, 0.f);
    float rs = rsqrtf(var + 1e-9f);
    float4 s = *reinterpret_cast<const float4*>(&g_self[(size_t)r * 128 + j]);
    float4 o;
    o.x = sc1[j + 0] * (t0 - mean) * rs + off1[j + 0] + s.x;
    o.y = sc1[j + 1] * (t1 - mean) * rs + off1[j + 1] + s.y;
    o.z = sc1[j + 2] * (t2 - mean) * rs + off1[j + 2] + s.z;
    o.w = sc1[j + 3] * (t3 - mean) * rs + off1[j + 3] + s.w;
    *reinterpret_cast<float4*>(&out[(size_t)r * 128 + j]) = o;
}

// ---------------- launch ----------------------------------------------------
extern "C" void kernel_launch(void* const* d_in, const int* in_sizes, int n_in,
                              void* d_out, int out_size) {
    const float* vecs     = (const float*)d_in[0];
    const float* adj_vals = (const float*)d_in[1];
    const float* W0       = (const float*)d_in[2];
    const float* b0       = (const float*)d_in[3];
    const float* W1       = (const float*)d_in[4];
    const float* b1       = (const float*)d_in[5];
    const float* att0     = (const float*)d_in[6];
    const float* att1     = (const float*)d_in[7];
    const float* attb0    = (const float*)d_in[8];
    const float* attb1    = (const float*)d_in[9];
    const float* off0     = (const float*)d_in[10];
    const float* sc0      = (const float*)d_in[11];
    const float* off1     = (const float*)d_in[12];
    const float* sc1      = (const float*)d_in[13];
    const int*   rows     = (const int*)d_in[14];
    const int*   cols     = (const int*)d_in[15];

    int n = in_sizes[0] / 128;
    int e = in_sizes[1];
    float* out = (float*)d_out;

    int nb = (n + 255) / 256;
    int nbp = nb < 128 ? 128 : nb;
    int ntiles = (n + 127) / 128;
    int grid = ntiles < 152 ? ntiles : 152;

    static cudaStream_t s2 = nullptr;
    static cudaEvent_t ev_fork = nullptr, ev_join = nullptr;
    static int smem_set = 0;
    if (!smem_set) {
        cudaFuncSetAttribute(gemm_tc_kernel, cudaFuncAttributeMaxDynamicSharedMemorySize,
                             SMEM_TOTAL);
        cudaStreamCreateWithFlags(&s2, cudaStreamNonBlocking);
        cudaEventCreateWithFlags(&ev_fork, cudaEventDisableTiming);
        cudaEventCreateWithFlags(&ev_join, cudaEventDisableTiming);
        smem_set = 1;
    }

    pack_kernel<<<nbp, 256>>>(W0, W1, n);
    cudaEventRecord(ev_fork, 0);
    cudaStreamWaitEvent(s2, ev_fork, 0);

    // side stream: entire CSR build, independent of the GEMM
    hist_kernel<<<(e + 255) / 256, 256, 0, s2>>>(rows, e);
    scan_kernel<<<nb, 256, 0, s2>>>(n);
    scatter_kernel<<<(e + 255) / 256, 256, 0, s2>>>(adj_vals, rows, cols, e);
    cudaEventRecord(ev_join, s2);

    // main stream: gemm concurrent with CSR build
    gemm_tc_kernel<<<grid, 256, SMEM_TOTAL>>>(vecs, b0, att0, att1, attb0, attb1,
                                              off0, sc0, n, ntiles);
    cudaStreamWaitEvent(0, ev_join, 0);

    agg_kernel<<<(n + 7) / 8, 256>>>(b1, off1, sc1, out, n);
}